// round 11
// baseline (speedup 1.0000x reference)
#include <cuda_runtime.h>
#include <cuda_fp16.h>
#include <math.h>
#include <stdint.h>

#define FN 360
#define BGRAPH 128
#define NNODE (FN*BGRAPH)
#define NEDGE 1000000
#define CCH 128
#define TRI 64980
#define D1 65364
#define ZP 65536
#define H1 512
#define H2 256
#define EPSV 1e-5f
#define PADK 136
#define AP 384

// ---------------- scratch ----------------
__device__ __align__(16) float  g_dinv[NNODE];
__device__ __align__(16) float  g_A [(size_t)BGRAPH*AP*AP];   // fp32 atomic build
__device__ __align__(16) __half g_Ah[(size_t)BGRAPH*AP*AP];   // fp16, ilv16 k
__device__ __align__(16) __half g_xh[(size_t)NNODE*AP];       // fp16 x, ilv16 k
__device__ __align__(16) __half g_wh[(size_t)3*CCH*AP];       // fp16 W^T, ilv16 k
__device__ __align__(16) __half g_hh[(size_t)BGRAPH*CCH*AP];  // fp16 h^T [b][c][j ilv16]
__device__ __align__(16) __half g_x1h[(size_t)NNODE*CCH];
__device__ __align__(16) __half g_x2h[(size_t)NNODE*CCH];
__device__ __align__(16) __half g_x3h[(size_t)NNODE*CCH];
__device__ __align__(16) __half g_zh[(size_t)BGRAPH*ZP];      // fp16 z, ilv16 cols
__device__ __align__(16) __half g_w1h[(size_t)H1*ZP];         // fp16 W1^T [n][k ilv16]
__device__ __align__(16) float  g_hpool[BGRAPH*384];
__device__ __align__(16) float  g_a1[BGRAPH*H1];
__device__ __align__(16) float  g_a2[BGRAPH*H2];
__device__ __align__(16) float  g_a3[BGRAPH*H2];

// ---------------- helpers ----------------
__device__ __forceinline__ uint32_t f2tf(float f) {
    uint32_t u; asm("cvt.rna.tf32.f32 %0, %1;" : "=r"(u) : "f"(f)); return u;
}
__device__ __forceinline__ float rndtf(float f) { return __uint_as_float(f2tf(f)); }
// fp16: interleave 16-groups so halfs at pos 4kt..4kt+3 are k = {2kt,2kt+1,2kt+8,2kt+9}
__device__ __forceinline__ int pl16(int j)  { int p=j>>1, b=j&1; return ((p&3)<<2)|(((p>>2)&1)<<1)|b; }
__device__ __forceinline__ int ilv16(int c) { return (c & ~15) + pl16(c & 15); }
__device__ __forceinline__ int orig16p(int q){ int b=q&1, t=(q>>1)&7; int p=((t&1)<<2)|(t>>1); return 2*p+b; }
__device__ __forceinline__ float fast_tanh(float x) {
    float e = __expf(2.0f*x);
    return 1.0f - __fdividef(2.0f, e + 1.0f);
}
__device__ __forceinline__ uint32_t s2u(const void* p) {
    uint32_t a;
    asm("{ .reg .u64 t; cvta.to.shared.u64 t, %1; cvt.u32.u64 %0, t; }" : "=r"(a) : "l"(p));
    return a;
}
__device__ __forceinline__ void cpa16(uint32_t d, const void* g) {
    asm volatile("cp.async.cg.shared.global [%0], [%1], 16;" :: "r"(d), "l"(g));
}
__device__ __forceinline__ void mma8(float* c, const uint32_t* a, const uint32_t* b) {
    asm volatile("mma.sync.aligned.m16n8k8.row.col.f32.tf32.tf32.f32 "
        "{%0,%1,%2,%3}, {%4,%5,%6,%7}, {%8,%9}, {%0,%1,%2,%3};"
        : "+f"(c[0]), "+f"(c[1]), "+f"(c[2]), "+f"(c[3])
        : "r"(a[0]), "r"(a[1]), "r"(a[2]), "r"(a[3]), "r"(b[0]), "r"(b[1]));
}
__device__ __forceinline__ void mma16(float* c, const uint32_t* a, const uint32_t* b) {
    asm volatile("mma.sync.aligned.m16n8k16.row.col.f32.f16.f16.f32 "
        "{%0,%1,%2,%3}, {%4,%5,%6,%7}, {%8,%9}, {%0,%1,%2,%3};"
        : "+f"(c[0]), "+f"(c[1]), "+f"(c[2]), "+f"(c[3])
        : "r"(a[0]), "r"(a[1]), "r"(a[2]), "r"(a[3]), "r"(b[0]), "r"(b[1]));
}

// ---------------- prep ----------------
__global__ void k_prep(const float* __restrict__ Wc1, const float* __restrict__ Wc2,
                       const float* __restrict__ Wc3) {
    int i = blockIdx.x*blockDim.x + threadIdx.x;
    if (i >= 3*CCH*(AP/16)) return;
    int w = i / (CCH*(AP/16));
    int r = (i / (AP/16)) % CCH;
    int grp = i % (AP/16);
    const float* W = (w==0) ? Wc1 : (w==1) ? Wc2 : Wc3;
    int KW = (w==0) ? FN : CCH;
    __align__(16) __half o[16];
    #pragma unroll
    for (int j = 0; j < 16; j++) {
        int k = grp*16 + j;
        o[pl16(j)] = (k < KW) ? __float2half_rn(W[k*CCH + r]) : __half(0.f);
    }
    __half* dst = g_wh + ((size_t)(w*CCH + r))*AP + grp*16;
    ((uint4*)dst)[0] = ((uint4*)o)[0];
    ((uint4*)dst)[1] = ((uint4*)o)[1];
}
__global__ void k_xh(const float* __restrict__ x) {
    int i = blockIdx.x*blockDim.x + threadIdx.x;
    if (i >= NNODE*(AP/16)) return;
    int n = i / (AP/16), grp = i % (AP/16);
    __align__(16) __half o[16];
    #pragma unroll
    for (int j = 0; j < 16; j++) {
        int k = grp*16 + j;
        o[pl16(j)] = (k < FN) ? __float2half_rn(x[(size_t)n*FN + k]) : __half(0.f);
    }
    __half* dst = g_xh + (size_t)n*AP + grp*16;
    ((uint4*)dst)[0] = ((uint4*)o)[0];
    ((uint4*)dst)[1] = ((uint4*)o)[1];
}
// W1 [D1][H1] fp32 -> g_w1h [H1][ZP] fp16, k interleaved; zeros for k >= D1
__global__ void k_w1h(const float* __restrict__ W1) {
    int i = blockIdx.x*blockDim.x + threadIdx.x;
    if (i >= H1*(ZP/16)) return;
    int n = i & (H1-1);
    int grp = i >> 9;
    __align__(16) __half o[16];
    #pragma unroll
    for (int j = 0; j < 16; j++) {
        int k = grp*16 + j;
        o[pl16(j)] = (k < D1) ? __float2half_rn(W1[(size_t)k*H1 + n]) : __half(0.f);
    }
    __half* dst = g_w1h + (size_t)n*ZP + grp*16;
    ((uint4*)dst)[0] = ((uint4*)o)[0];
    ((uint4*)dst)[1] = ((uint4*)o)[1];
}
__global__ void k_count_deg(const int* __restrict__ dst) {
    int i = blockIdx.x*blockDim.x + threadIdx.x;
    if (i < NEDGE) atomicAdd(&g_dinv[dst[i]], 1.0f);
}
__global__ void k_make_dinv() {
    int i = blockIdx.x*blockDim.x + threadIdx.x;
    if (i < NNODE) g_dinv[i] = rsqrtf(g_dinv[i] + 1.0f);
}
__global__ void k_build(const int* __restrict__ src, const int* __restrict__ dst) {
    int i = blockIdx.x*blockDim.x + threadIdx.x;
    if (i < NEDGE) {
        int d = dst[i], s = src[i];
        int b = d / FN, r = d - b*FN, c = s - b*FN;
        atomicAdd(&g_A[((size_t)b*AP + r)*AP + c], g_dinv[s]*g_dinv[d]);
    } else if (i < NEDGE + NNODE) {
        int n = i - NEDGE, b = n / FN, r = n - b*FN;
        atomicAdd(&g_A[((size_t)b*AP + r)*AP + r], g_dinv[n]*g_dinv[n]);
    }
}
__global__ void k_convA() {
    size_t stride = (size_t)gridDim.x*blockDim.x;
    size_t tot = (size_t)BGRAPH*AP*AP/16;
    for (size_t i = blockIdx.x*blockDim.x + threadIdx.x; i < tot; i += stride) {
        const float* p = g_A + i*16;
        float in[16];
        #pragma unroll
        for (int q = 0; q < 4; q++) {
            float4 v = ((const float4*)p)[q];
            in[q*4+0]=v.x; in[q*4+1]=v.y; in[q*4+2]=v.z; in[q*4+3]=v.w;
        }
        __align__(16) __half o[16];
        #pragma unroll
        for (int j = 0; j < 16; j++) o[pl16(j)] = __float2half_rn(in[j]);
        __half* dst = g_Ah + i*16;
        ((uint4*)dst)[0] = ((uint4*)o)[0];
        ((uint4*)dst)[1] = ((uint4*)o)[1];
    }
}

// ---------------- fp16 HMMA GEMM, BK=64, 2-stage cp.async ----------------
// 128x128 tile, 256 thr (8 warps 2x4, warp 64x32). A [m][k ilv16], B [n][k ilv16].
// MODE 0: XW -> g_hh[(b*CCH+c)*AP + ilv16(j)]. grid(360)
// MODE 1: AH -> xs fp16 = tanh(D+bias). grid(3, BGRAPH), y = graph
// MODE 2: zW1 split-K: grid(1, H1/128, 64); kbeg = z*1024, B rows = y*128 + n;
//         fp32 atomicAdd into Cf[M x H1]. All pads zeroed, no clamping.
template<int MODE>
__global__ __launch_bounds__(256)
void gkh(const __half* __restrict__ Ag, const __half* __restrict__ Bg,
         const float* __restrict__ bias, __half* __restrict__ Cg,
         float* __restrict__ Cf, int lda, int ldb, int M, int K)
{
    extern __shared__ __align__(16) __half dynh[];
    const int RP = 80;                      // halfs per smem row (64 + pad)
    const int STG = 2*128*RP;               // halfs per stage (A + B)
    const int tid = threadIdx.x, lane = tid & 31, w = tid >> 5;
    const int wm = (w & 1)*64, wn = (w >> 1)*32;
    const int g = lane >> 2, kt = lane & 3;
    const int rowBase = blockIdx.x*128;
    const int bOff = (MODE == 2) ? blockIdx.y*128 : 0;

    if (MODE == 1) {
        Ag += (size_t)blockIdx.y * AP * AP;
        Bg += (size_t)blockIdx.y * CCH * AP;
    }
    const int kbeg = (MODE == 2) ? blockIdx.z*1024 : 0;
    const int am = tid >> 1;                // row (A and B), 2 threads/row
    const int ak = (tid & 1) * 32;          // 32-half block within 64-half row

    auto load_chunk = [&](int c, int stg) {
        int k0 = kbeg + c*64;
        __half* As = dynh + stg*STG;
        __half* Bs = As + 128*RP;
        const __half* ar = Ag + (size_t)(rowBase + am)*lda + k0 + ak;
        uint32_t ad = s2u(As + am*RP + ak);
        cpa16(ad,      ar);
        cpa16(ad + 16, ar + 8);
        cpa16(ad + 32, ar + 16);
        cpa16(ad + 48, ar + 24);
        const __half* br = Bg + (size_t)(bOff + am)*ldb + k0 + ak;
        uint32_t bd = s2u(Bs + am*RP + ak);
        cpa16(bd,      br);
        cpa16(bd + 16, br + 8);
        cpa16(bd + 32, br + 16);
        cpa16(bd + 48, br + 24);
        asm volatile("cp.async.commit_group;" ::: "memory");
    };

    float acc[4][4][4];
    #pragma unroll
    for (int mi = 0; mi < 4; mi++)
        #pragma unroll
        for (int nj = 0; nj < 4; nj++)
            #pragma unroll
            for (int r = 0; r < 4; r++) acc[mi][nj][r] = 0.f;

    const int nch = K >> 6;
    load_chunk(0, 0);
    for (int c = 0; c < nch; c++) {
        int buf = c & 1;
        if (c + 1 < nch) {
            load_chunk(c + 1, buf ^ 1);
            asm volatile("cp.async.wait_group 1;" ::: "memory");
        } else {
            asm volatile("cp.async.wait_group 0;" ::: "memory");
        }
        __syncthreads();
        const __half* As = dynh + buf*STG;
        const __half* Bs = As + 128*RP;
        #pragma unroll
        for (int ks = 0; ks < 4; ks++) {
            uint32_t af[4][4], bf[4][2];
            #pragma unroll
            for (int mi = 0; mi < 4; mi++) {
                int m = wm + mi*16 + g;
                uint2 va = *(const uint2*)&As[m*RP     + ks*16 + 4*kt];
                uint2 vb = *(const uint2*)&As[(m+8)*RP + ks*16 + 4*kt];
                af[mi][0] = va.x;
                af[mi][1] = vb.x;
                af[mi][2] = va.y;
                af[mi][3] = vb.y;
            }
            #pragma unroll
            for (int nj = 0; nj < 4; nj++) {
                int n = wn + nj*8 + g;
                uint2 u = *(const uint2*)&Bs[n*RP + ks*16 + 4*kt];
                bf[nj][0] = u.x;
                bf[nj][1] = u.y;
            }
            #pragma unroll
            for (int mi = 0; mi < 4; mi++)
                #pragma unroll
                for (int nj = 0; nj < 4; nj++)
                    mma16(acc[mi][nj], af[mi], bf[nj]);
        }
        __syncthreads();
    }

    #pragma unroll
    for (int mi = 0; mi < 4; mi++)
        #pragma unroll
        for (int nj = 0; nj < 4; nj++)
            #pragma unroll
            for (int r = 0; r < 4; r++) {
                int gm = rowBase + wm + mi*16 + g + (r>>1)*8;
                int gn = wn + nj*8 + kt*2 + (r&1);
                float v = acc[mi][nj][r];
                if (MODE == 0) {
                    int b = gm / FN, j = gm - b*FN;
                    g_hh[((size_t)b*CCH + gn)*AP + ilv16(j)] = __float2half_rn(v);
                } else if (MODE == 1) {
                    if (gm < M) {
                        __half* dst = Cg + ((size_t)blockIdx.y*FN + gm)*CCH;
                        dst[ilv16(gn)] = __float2half_rn(fast_tanh(v + __ldg(bias + gn)));
                    }
                } else {
                    atomicAdd(&Cf[(size_t)gm*H1 + bOff + gn], v);
                }
            }
}

// ---------------- legacy tf32 mma.sync GEMM (small MLP layers) ----------------
__global__ __launch_bounds__(256)
void mmak(const float* __restrict__ A, const float* __restrict__ Bm,
          float* __restrict__ C, int M, int N, int K)
{
    __shared__ uint32_t As[2][16][PADK];
    __shared__ uint32_t Bs[2][16][PADK];
    const int tid = threadIdx.x, lane = tid & 31, w = tid >> 5;
    const int wm = (w & 1)*64, wn = (w >> 1)*32;
    const int g = lane >> 2, kt = lane & 3;
    const int rowBase = blockIdx.x*128, colBase = blockIdx.y*128;
    const int aRow = tid >> 1, aCol = (tid & 1)*8;
    const int bRow = tid >> 4, bCol = (tid & 15)*8;
    float acc[4][4][4];
    #pragma unroll
    for (int mi = 0; mi < 4; mi++)
        #pragma unroll
        for (int nj = 0; nj < 4; nj++)
            #pragma unroll
            for (int r = 0; r < 4; r++) acc[mi][nj][r] = 0.f;
    const int gmA = rowBase + aRow;
    float4 pa[2], pb[2];
    auto loadT = [&](int k0) {
        #pragma unroll
        for (int h = 0; h < 2; h++) {
            int gk = k0 + aCol + h*4;
            float4 v = make_float4(0.f,0.f,0.f,0.f);
            if (gmA < M && gk + 3 < K) v = *(const float4*)(A + (size_t)gmA*K + gk);
            pa[h] = v;
        }
        int gk = k0 + bRow;
        #pragma unroll
        for (int h = 0; h < 2; h++) {
            int gn = colBase + bCol + h*4;
            float4 v = make_float4(0.f,0.f,0.f,0.f);
            if (gk < K && gn < N) v = *(const float4*)(Bm + (size_t)gk*N + gn);
            pb[h] = v;
        }
    };
    auto storeT = [&](int buf) {
        #pragma unroll
        for (int h = 0; h < 2; h++) {
            As[buf][aCol+h*4+0][aRow] = f2tf(pa[h].x);
            As[buf][aCol+h*4+1][aRow] = f2tf(pa[h].y);
            As[buf][aCol+h*4+2][aRow] = f2tf(pa[h].z);
            As[buf][aCol+h*4+3][aRow] = f2tf(pa[h].w);
            Bs[buf][bRow][bCol+h*4+0] = f2tf(pb[h].x);
            Bs[buf][bRow][bCol+h*4+1] = f2tf(pb[h].y);
            Bs[buf][bRow][bCol+h*4+2] = f2tf(pb[h].z);
            Bs[buf][bRow][bCol+h*4+3] = f2tf(pb[h].w);
        }
    };
    auto comp = [&](int buf) {
        #pragma unroll
        for (int ks = 0; ks < 2; ks++) {
            uint32_t af[4][4], bf[4][2];
            #pragma unroll
            for (int mi = 0; mi < 4; mi++) {
                int m = wm + mi*16;
                af[mi][0] = As[buf][ks*8+kt  ][m+g  ];
                af[mi][1] = As[buf][ks*8+kt  ][m+g+8];
                af[mi][2] = As[buf][ks*8+kt+4][m+g  ];
                af[mi][3] = As[buf][ks*8+kt+4][m+g+8];
            }
            #pragma unroll
            for (int nj = 0; nj < 4; nj++) {
                int n = wn + nj*8;
                bf[nj][0] = Bs[buf][ks*8+kt  ][n+g];
                bf[nj][1] = Bs[buf][ks*8+kt+4][n+g];
            }
            #pragma unroll
            for (int mi = 0; mi < 4; mi++)
                #pragma unroll
                for (int nj = 0; nj < 4; nj++) mma8(acc[mi][nj], af[mi], bf[nj]);
        }
    };
    const int nIter = (K + 15) >> 4;
    loadT(0); storeT(0); __syncthreads();
    for (int t = 1; t < nIter; t++) {
        loadT(t*16);
        comp((t-1) & 1);
        storeT(t & 1);
        __syncthreads();
    }
    comp((nIter-1) & 1);
    #pragma unroll
    for (int mi = 0; mi < 4; mi++)
        #pragma unroll
        for (int nj = 0; nj < 4; nj++)
            #pragma unroll
            for (int r = 0; r < 4; r++) {
                int gm = rowBase + wm + mi*16 + g + (r>>1)*8;
                int gn = colBase + wn + nj*8 + kt*2 + (r&1);
                if (gm < M && gn < N) C[(size_t)gm*N + gn] = acc[mi][nj][r];
            }
}

// ---------------- BN / pool / head ----------------
__global__ void k_x0_bn(const float* __restrict__ x, const float* __restrict__ g,
                        const float* __restrict__ be, __half* __restrict__ z)
{
    int r = blockIdx.x;
    int c = r + threadIdx.x;
    if (c >= FN) return;
    long j = (long)r*FN - (long)r*(r-1)/2 + (c - r);
    long zi = (j & ~15L) + pl16((int)(j & 15));
    float s = 0.f, ss = 0.f;
    for (int b = 0; b < BGRAPH; b++) {
        float v = x[((size_t)(b*FN + r))*FN + c];
        s += v; ss += v*v;
    }
    float m = s*(1.f/BGRAPH);
    float var = ss*(1.f/BGRAPH) - m*m;
    float sc = rsqrtf(var + EPSV)*g[j];
    float bb = be[j];
    for (int b = 0; b < BGRAPH; b++) {
        float v = x[((size_t)(b*FN + r))*FN + c];
        z[(size_t)b*ZP + zi] = __float2half_rn((v - m)*sc + bb);
    }
}
__global__ void k_pool(const __half* __restrict__ x1, const __half* __restrict__ x2,
                       const __half* __restrict__ x3, float* __restrict__ hp)
{
    int b = blockIdx.x, l = blockIdx.y, k = threadIdx.x;
    const __half* base = (l==0 ? x1 : l==1 ? x2 : x3) + (size_t)b*FN*CCH + k;
    float s0=0.f, s1=0.f, s2=0.f, s3=0.f;
    #pragma unroll 1
    for (int n = 0; n < FN; n += 4) {
        s0 += __half2float(base[(size_t)(n+0)*CCH]);
        s1 += __half2float(base[(size_t)(n+1)*CCH]);
        s2 += __half2float(base[(size_t)(n+2)*CCH]);
        s3 += __half2float(base[(size_t)(n+3)*CCH]);
    }
    int oc = (k & ~15) + orig16p(k & 15);
    hp[b*384 + l*CCH + oc] = (s0+s1+s2+s3)*(1.0f/FN);
}
// j in [0,384): BN of pooled; j in [384, ZP-TRI): zero pad cols of z
__global__ void k_bn_pool(const float* __restrict__ hp, const float* __restrict__ g,
                          const float* __restrict__ be, __half* __restrict__ z)
{
    int j = blockIdx.x*blockDim.x + threadIdx.x;
    if (j >= ZP - TRI) return;
    long cg2 = (long)TRI + j;
    long zi = (cg2 & ~15L) + pl16((int)(cg2 & 15));
    if (j >= 384) {
        for (int b = 0; b < BGRAPH; b++) z[(size_t)b*ZP + zi] = __half(0.f);
        return;
    }
    float s = 0.f, ss = 0.f;
    for (int b = 0; b < BGRAPH; b++) { float v = hp[b*384 + j]; s += v; ss += v*v; }
    float m = s*(1.f/BGRAPH);
    float var = ss*(1.f/BGRAPH) - m*m;
    float sc = rsqrtf(var + EPSV)*g[j];
    float bb = be[j];
    for (int b = 0; b < BGRAPH; b++)
        z[(size_t)b*ZP + zi] = __float2half_rn((hp[b*384 + j] - m)*sc + bb);
}
__global__ void k_bn_relu(const float* __restrict__ X, const float* __restrict__ bias,
                          const float* __restrict__ gam, const float* __restrict__ bet,
                          float* __restrict__ Y, int ncols)
{
    int col = blockIdx.x, t = threadIdx.x;
    float v = X[t*ncols + col] + bias[col];
    float s = v, ss = v*v;
    #pragma unroll
    for (int o = 16; o > 0; o >>= 1) {
        s  += __shfl_down_sync(0xffffffffu, s,  o);
        ss += __shfl_down_sync(0xffffffffu, ss, o);
    }
    __shared__ float ws[4], wss[4];
    __shared__ float sm, sscale;
    int wid = t >> 5, lane = t & 31;
    if (lane == 0) { ws[wid] = s; wss[wid] = ss; }
    __syncthreads();
    if (t == 0) {
        float S = ws[0]+ws[1]+ws[2]+ws[3];
        float SS = wss[0]+wss[1]+wss[2]+wss[3];
        float m = S*(1.f/BGRAPH);
        sm = m; sscale = rsqrtf(SS*(1.f/BGRAPH) - m*m + EPSV);
    }
    __syncthreads();
    float o = (v - sm)*sscale*gam[col] + bet[col];
    Y[t*ncols + col] = fmaxf(o, 0.f);
}
__global__ void k_head(const float* __restrict__ a3, const float* __restrict__ W4,
                       const float* __restrict__ b4, float* __restrict__ out)
{
    int b = blockIdx.x, lane = threadIdx.x;
    float s0 = 0.f, s1 = 0.f;
    for (int i = lane; i < H2; i += 32) {
        float v = a3[b*H2 + i];
        s0 = fmaf(v, W4[i*2+0], s0);
        s1 = fmaf(v, W4[i*2+1], s1);
    }
    #pragma unroll
    for (int o = 16; o > 0; o >>= 1) {
        s0 += __shfl_down_sync(0xffffffffu, s0, o);
        s1 += __shfl_down_sync(0xffffffffu, s1, o);
    }
    if (lane == 0) {
        float l0 = s0 + b4[0], l1 = s1 + b4[1];
        float m = fmaxf(l0, l1);
        float lse = m + logf(expf(l0-m) + expf(l1-m));
        out[b*2+0] = l0 - lse;
        out[b*2+1] = l1 - lse;
    }
}

// ---------------- launch ----------------
extern "C" void kernel_launch(void* const* d_in, const int* in_sizes, int n_in,
                              void* d_out, int out_size)
{
    const float* x    = (const float*)d_in[0];
    const int*   esrc = (const int*)d_in[1];
    const int*   edst = (const int*)d_in[2];
    const float* Wc1  = (const float*)d_in[4];
    const float* bc1  = (const float*)d_in[5];
    const float* Wc2  = (const float*)d_in[6];
    const float* bc2  = (const float*)d_in[7];
    const float* Wc3  = (const float*)d_in[8];
    const float* bc3  = (const float*)d_in[9];
    const float* bn_g = (const float*)d_in[10];
    const float* bn_b = (const float*)d_in[11];
    const float* bnh_g= (const float*)d_in[12];
    const float* bnh_b= (const float*)d_in[13];
    const float* W1   = (const float*)d_in[14];
    const float* b1   = (const float*)d_in[15];
    const float* g1   = (const float*)d_in[16];
    const float* be1  = (const float*)d_in[17];
    const float* W2   = (const float*)d_in[18];
    const float* b2   = (const float*)d_in[19];
    const float* g2   = (const float*)d_in[20];
    const float* be2  = (const float*)d_in[21];
    const float* W3   = (const float*)d_in[22];
    const float* b3   = (const float*)d_in[23];
    const float* g3   = (const float*)d_in[24];
    const float* be3  = (const float*)d_in[25];
    const float* W4   = (const float*)d_in[26];
    const float* b4   = (const float*)d_in[27];
    float* out = (float*)d_out;

    const int DSMH = 2*(2*128*80)*2;   // 81920 B (fp16 GEMM, BK=64, 2 stages)
    cudaFuncSetAttribute(gkh<0>, cudaFuncAttributeMaxDynamicSharedMemorySize, DSMH);
    cudaFuncSetAttribute(gkh<1>, cudaFuncAttributeMaxDynamicSharedMemorySize, DSMH);
    cudaFuncSetAttribute(gkh<2>, cudaFuncAttributeMaxDynamicSharedMemorySize, DSMH);

    void *pDinv, *pA, *pAh, *pXh, *pHh, *pX1, *pX2, *pX3, *pZh, *pW1h, *pHp, *pA1, *pA2, *pA3, *pWh;
    cudaGetSymbolAddress(&pDinv, g_dinv);
    cudaGetSymbolAddress(&pA,   g_A);
    cudaGetSymbolAddress(&pAh,  g_Ah);
    cudaGetSymbolAddress(&pXh,  g_xh);
    cudaGetSymbolAddress(&pHh,  g_hh);
    cudaGetSymbolAddress(&pX1,  g_x1h);
    cudaGetSymbolAddress(&pX2,  g_x2h);
    cudaGetSymbolAddress(&pX3,  g_x3h);
    cudaGetSymbolAddress(&pZh,  g_zh);
    cudaGetSymbolAddress(&pW1h, g_w1h);
    cudaGetSymbolAddress(&pHp,  g_hpool);
    cudaGetSymbolAddress(&pA1,  g_a1);
    cudaGetSymbolAddress(&pA2,  g_a2);
    cudaGetSymbolAddress(&pA3,  g_a3);
    cudaGetSymbolAddress(&pWh,  g_wh);

    const __half* wh = (const __half*)pWh;
    const __half* xh = (const __half*)pXh;
    const __half* Ah = (const __half*)pAh;
    const __half* hh = (const __half*)pHh;
    const __half* zh = (const __half*)pZh;
    const __half* w1h = (const __half*)pW1h;

    // launch order: first fp16 GEMM at index 6 (ncu capture slot)
    cudaMemsetAsync(pHh, 0, (size_t)BGRAPH*CCH*AP*2, 0);             // 0
    cudaMemsetAsync(pDinv, 0, (size_t)NNODE*4, 0);                   // 1
    cudaMemsetAsync(pA, 0, (size_t)BGRAPH*AP*AP*4, 0);               // 2
    k_count_deg<<<(NEDGE+255)/256, 256>>>(edst);                     // 3
    k_prep<<<(3*CCH*(AP/16)+255)/256, 256>>>(Wc1, Wc2, Wc3);         // 4
    k_xh<<<(NNODE*(AP/16)+255)/256, 256>>>(x);                       // 5
    gkh<0><<<dim3(360,1), 256, DSMH>>>(xh, wh, nullptr, nullptr, nullptr,   // 6 <- ncu
                                       AP, AP, NNODE, AP);
    k_make_dinv<<<(NNODE+255)/256, 256>>>();                         // 7
    k_build<<<(NEDGE+NNODE+255)/256, 256>>>(esrc, edst);             // 8
    k_convA<<<2048, 256>>>();                                        // 9
    k_w1h<<<(H1*(ZP/16)+255)/256, 256>>>(W1);                        // 10

    gkh<1><<<dim3(3,BGRAPH), 256, DSMH>>>(Ah, hh, bc1, (__half*)pX1, nullptr, AP, AP, FN, AP);
    gkh<0><<<dim3(360,1), 256, DSMH>>>((const __half*)pX1, wh + (size_t)CCH*AP, nullptr, nullptr,
                                       nullptr, CCH, AP, NNODE, CCH);
    gkh<1><<<dim3(3,BGRAPH), 256, DSMH>>>(Ah, hh, bc2, (__half*)pX2, nullptr, AP, AP, FN, AP);
    gkh<0><<<dim3(360,1), 256, DSMH>>>((const __half*)pX2, wh + (size_t)2*CCH*AP, nullptr, nullptr,
                                       nullptr, CCH, AP, NNODE, CCH);
    gkh<1><<<dim3(3,BGRAPH), 256, DSMH>>>(Ah, hh, bc3, (__half*)pX3, nullptr, AP, AP, FN, AP);

    // features
    k_x0_bn<<<FN, 384>>>(x, bn_g, bn_b, (__half*)pZh);
    k_pool<<<dim3(BGRAPH,3), CCH>>>((const __half*)pX1, (const __half*)pX2,
                                    (const __half*)pX3, (float*)pHp);
    k_bn_pool<<<1, 1024>>>((const float*)pHp, bnh_g, bnh_b, (__half*)pZh);

    // MLP head: zW1 fp16 split-K, then tf32 small layers
    cudaMemsetAsync(pA1, 0, (size_t)BGRAPH*H1*4, 0);
    gkh<2><<<dim3(1,4,64), 256, DSMH>>>(zh, w1h, nullptr, nullptr, (float*)pA1,
                                        ZP, ZP, BGRAPH, 1024);
    k_bn_relu<<<H1, 128>>>((const float*)pA1, b1, g1, be1, (float*)pA1, H1);
    mmak<<<dim3(1,2), 256>>>((const float*)pA1, W2, (float*)pA2, BGRAPH, H2, H1);
    k_bn_relu<<<H2, 128>>>((const float*)pA2, b2, g2, be2, (float*)pA2, H2);
    mmak<<<dim3(1,2), 256>>>((const float*)pA2, W3, (float*)pA3, BGRAPH, H2, H2);
    k_bn_relu<<<H2, 128>>>((const float*)pA3, b3, g3, be3, (float*)pA3, H2);
    k_head<<<BGRAPH, 32>>>((const float*)pA3, W4, b4, out);
}

// round 12
// speedup vs baseline: 1.0417x; 1.0417x over previous
#include <cuda_runtime.h>
#include <cuda_fp16.h>
#include <math.h>
#include <stdint.h>

#define FN 360
#define BGRAPH 128
#define NNODE (FN*BGRAPH)
#define NEDGE 1000000
#define CCH 128
#define TRI 64980
#define D1 65364
#define ZP 65536
#define H1 512
#define H2 256
#define EPSV 1e-5f
#define PADK 136
#define AP 384

// ---------------- scratch ----------------
__device__ __align__(16) float  g_dinv[NNODE];
__device__ __align__(16) __half g_Ah[(size_t)BGRAPH*AP*AP];   // fp16 adjacency, ilv16 k
__device__ __align__(16) __half g_xh[(size_t)NNODE*AP];       // fp16 x, ilv16 k
__device__ __align__(16) __half g_wh[(size_t)3*CCH*AP];       // fp16 W^T, ilv16 k
__device__ __align__(16) __half g_hh[(size_t)BGRAPH*CCH*AP];  // fp16 h^T [b][c][j ilv16]
__device__ __align__(16) __half g_x1h[(size_t)NNODE*CCH];
__device__ __align__(16) __half g_x2h[(size_t)NNODE*CCH];
__device__ __align__(16) __half g_x3h[(size_t)NNODE*CCH];
__device__ __align__(16) __half g_zh[(size_t)BGRAPH*ZP];      // fp16 z, ilv16 cols
__device__ __align__(16) __half g_w1h[(size_t)H1*ZP];         // fp16 W1^T [n][k ilv16]
__device__ __align__(16) float  g_hpool[BGRAPH*384];
__device__ __align__(16) float  g_a1[BGRAPH*H1];
__device__ __align__(16) float  g_a2[BGRAPH*H2];
__device__ __align__(16) float  g_a3[BGRAPH*H2];

// ---------------- helpers ----------------
__device__ __forceinline__ uint32_t f2tf(float f) {
    uint32_t u; asm("cvt.rna.tf32.f32 %0, %1;" : "=r"(u) : "f"(f)); return u;
}
// fp16 ilv16: halfs at pos 4kt..4kt+3 hold k = {2kt,2kt+1,2kt+8,2kt+9}
__device__ __forceinline__ int pl16(int j)  { int p=j>>1, b=j&1; return ((p&3)<<2)|(((p>>2)&1)<<1)|b; }
__device__ __forceinline__ int ilv16(int c) { return (c & ~15) + pl16(c & 15); }
__device__ __forceinline__ int orig16p(int q){ int b=q&1, t=(q>>1)&7; int p=((t&1)<<2)|(t>>1); return 2*p+b; }
__device__ __forceinline__ float fast_tanh(float x) {
    float e = __expf(2.0f*x);
    return 1.0f - __fdividef(2.0f, e + 1.0f);
}
__device__ __forceinline__ uint32_t s2u(const void* p) {
    uint32_t a;
    asm("{ .reg .u64 t; cvta.to.shared.u64 t, %1; cvt.u32.u64 %0, t; }" : "=r"(a) : "l"(p));
    return a;
}
__device__ __forceinline__ void cpa16(uint32_t d, const void* g) {
    asm volatile("cp.async.cg.shared.global [%0], [%1], 16;" :: "r"(d), "l"(g));
}
__device__ __forceinline__ void mma8(float* c, const uint32_t* a, const uint32_t* b) {
    asm volatile("mma.sync.aligned.m16n8k8.row.col.f32.tf32.tf32.f32 "
        "{%0,%1,%2,%3}, {%4,%5,%6,%7}, {%8,%9}, {%0,%1,%2,%3};"
        : "+f"(c[0]), "+f"(c[1]), "+f"(c[2]), "+f"(c[3])
        : "r"(a[0]), "r"(a[1]), "r"(a[2]), "r"(a[3]), "r"(b[0]), "r"(b[1]));
}
__device__ __forceinline__ void mma16(float* c, const uint32_t* a, const uint32_t* b) {
    asm volatile("mma.sync.aligned.m16n8k16.row.col.f32.f16.f16.f32 "
        "{%0,%1,%2,%3}, {%4,%5,%6,%7}, {%8,%9}, {%0,%1,%2,%3};"
        : "+f"(c[0]), "+f"(c[1]), "+f"(c[2]), "+f"(c[3])
        : "r"(a[0]), "r"(a[1]), "r"(a[2]), "r"(a[3]), "r"(b[0]), "r"(b[1]));
}

// ---------------- prep ----------------
__global__ void k_prep(const float* __restrict__ Wc1, const float* __restrict__ Wc2,
                       const float* __restrict__ Wc3) {
    int i = blockIdx.x*blockDim.x + threadIdx.x;
    if (i >= 3*CCH*(AP/16)) return;
    int w = i / (CCH*(AP/16));
    int r = (i / (AP/16)) % CCH;
    int grp = i % (AP/16);
    const float* W = (w==0) ? Wc1 : (w==1) ? Wc2 : Wc3;
    int KW = (w==0) ? FN : CCH;
    __align__(16) __half o[16];
    #pragma unroll
    for (int j = 0; j < 16; j++) {
        int k = grp*16 + j;
        o[pl16(j)] = (k < KW) ? __float2half_rn(W[k*CCH + r]) : __half(0.f);
    }
    __half* dst = g_wh + ((size_t)(w*CCH + r))*AP + grp*16;
    ((uint4*)dst)[0] = ((uint4*)o)[0];
    ((uint4*)dst)[1] = ((uint4*)o)[1];
}
__global__ void k_xh(const float* __restrict__ x) {
    int i = blockIdx.x*blockDim.x + threadIdx.x;
    if (i >= NNODE*(AP/16)) return;
    int n = i / (AP/16), grp = i % (AP/16);
    __align__(16) __half o[16];
    #pragma unroll
    for (int j = 0; j < 16; j++) {
        int k = grp*16 + j;
        o[pl16(j)] = (k < FN) ? __float2half_rn(x[(size_t)n*FN + k]) : __half(0.f);
    }
    __half* dst = g_xh + (size_t)n*AP + grp*16;
    ((uint4*)dst)[0] = ((uint4*)o)[0];
    ((uint4*)dst)[1] = ((uint4*)o)[1];
}
// W1 [D1][H1] fp32 -> g_w1h [H1][ZP] fp16, k interleaved; zeros for k >= D1
__global__ void k_w1h(const float* __restrict__ W1) {
    int i = blockIdx.x*blockDim.x + threadIdx.x;
    if (i >= H1*(ZP/16)) return;
    int n = i & (H1-1);
    int grp = i >> 9;
    __align__(16) __half o[16];
    #pragma unroll
    for (int j = 0; j < 16; j++) {
        int k = grp*16 + j;
        o[pl16(j)] = (k < D1) ? __float2half_rn(W1[(size_t)k*H1 + n]) : __half(0.f);
    }
    __half* dst = g_w1h + (size_t)n*ZP + grp*16;
    ((uint4*)dst)[0] = ((uint4*)o)[0];
    ((uint4*)dst)[1] = ((uint4*)o)[1];
}
__global__ void k_count_deg(const int* __restrict__ dst) {
    int i = blockIdx.x*blockDim.x + threadIdx.x;
    if (i < NEDGE) atomicAdd(&g_dinv[dst[i]], 1.0f);
}
__global__ void k_make_dinv() {
    int i = blockIdx.x*blockDim.x + threadIdx.x;
    if (i < NNODE) g_dinv[i] = rsqrtf(g_dinv[i] + 1.0f);
}
// build adjacency directly in fp16 (ilv16 columns); g_Ah pre-zeroed
__global__ void k_build(const int* __restrict__ src, const int* __restrict__ dst) {
    int i = blockIdx.x*blockDim.x + threadIdx.x;
    if (i < NEDGE) {
        int d = dst[i], s = src[i];
        int b = d / FN, r = d - b*FN, c = s - b*FN;
        atomicAdd(&g_Ah[((size_t)b*AP + r)*AP + ilv16(c)],
                  __float2half_rn(g_dinv[s]*g_dinv[d]));
    } else if (i < NEDGE + NNODE) {
        int n = i - NEDGE, b = n / FN, r = n - b*FN;
        atomicAdd(&g_Ah[((size_t)b*AP + r)*AP + ilv16(r)],
                  __float2half_rn(g_dinv[n]*g_dinv[n]));
    }
}

// ---------------- fp16 HMMA GEMM, BK=32, 3-stage cp.async ----------------
// 128x128 tile, 256 thr (8 warps 2x4, warp 64x32). A [m][k ilv16], B [n][k ilv16].
// MODE 0: XW -> g_hh[(b*CCH+c)*AP + ilv16(j)]. grid(360)
// MODE 1: AH -> xs fp16 = tanh(D+bias). grid(3, BGRAPH), y = graph
// MODE 2: zW1 split-K: grid(1, H1/128, 64); kbeg = z*1024; B rows = y*128 + n;
//         fp32 atomicAdd into Cf. All pads zeroed.
template<int MODE>
__global__ __launch_bounds__(256)
void gkh(const __half* __restrict__ Ag, const __half* __restrict__ Bg,
         const float* __restrict__ bias, __half* __restrict__ Cg,
         float* __restrict__ Cf, int lda, int ldb, int M, int K)
{
    extern __shared__ __align__(16) __half dynh[];
    const int STG = 12288;                 // halfs/stage: A 128x48 + B 128x48
    const int tid = threadIdx.x, lane = tid & 31, w = tid >> 5;
    const int wm = (w & 1)*64, wn = (w >> 1)*32;
    const int g = lane >> 2, kt = lane & 3;
    const int rowBase = blockIdx.x*128;
    const int bOff = (MODE == 2) ? blockIdx.y*128 : 0;

    if (MODE == 1) {
        Ag += (size_t)blockIdx.y * AP * AP;
        Bg += (size_t)blockIdx.y * CCH * AP;
    }
    const int kbeg = (MODE == 2) ? blockIdx.z*1024 : 0;
    const int am = tid >> 1;               // row (A and B), 2 threads/row
    const int ak = (tid & 1) * 16;         // 16-half block within 32-half row

    auto load_chunk = [&](int c, int stg) {
        int k0 = kbeg + c*32;
        __half* As = dynh + stg*STG;
        __half* Bs = As + 6144;
        const __half* ar = Ag + (size_t)(rowBase + am)*lda + k0 + ak;
        uint32_t ad = s2u(As + am*48 + ak);
        cpa16(ad,      ar);
        cpa16(ad + 16, ar + 8);
        const __half* br = Bg + (size_t)(bOff + am)*ldb + k0 + ak;
        uint32_t bd = s2u(Bs + am*48 + ak);
        cpa16(bd,      br);
        cpa16(bd + 16, br + 8);
        asm volatile("cp.async.commit_group;" ::: "memory");
    };

    float acc[4][4][4];
    #pragma unroll
    for (int mi = 0; mi < 4; mi++)
        #pragma unroll
        for (int nj = 0; nj < 4; nj++)
            #pragma unroll
            for (int r = 0; r < 4; r++) acc[mi][nj][r] = 0.f;

    const int nch = K >> 5;
    load_chunk(0, 0);
    load_chunk(1, 1);
    for (int c = 0; c < nch; c++) {
        int buf = c % 3;
        if (c + 2 < nch) {
            load_chunk(c + 2, (c + 2) % 3);
            asm volatile("cp.async.wait_group 2;" ::: "memory");
        } else if (c + 1 < nch) {
            asm volatile("cp.async.wait_group 1;" ::: "memory");
        } else {
            asm volatile("cp.async.wait_group 0;" ::: "memory");
        }
        __syncthreads();
        const __half* As = dynh + buf*STG;
        const __half* Bs = As + 6144;
        #pragma unroll
        for (int ks = 0; ks < 2; ks++) {
            uint32_t af[4][4], bf[4][2];
            #pragma unroll
            for (int mi = 0; mi < 4; mi++) {
                int m = wm + mi*16 + g;
                uint2 va = *(const uint2*)&As[m*48     + ks*16 + 4*kt];
                uint2 vb = *(const uint2*)&As[(m+8)*48 + ks*16 + 4*kt];
                af[mi][0] = va.x;
                af[mi][1] = vb.x;
                af[mi][2] = va.y;
                af[mi][3] = vb.y;
            }
            #pragma unroll
            for (int nj = 0; nj < 4; nj++) {
                int n = wn + nj*8 + g;
                uint2 u = *(const uint2*)&Bs[n*48 + ks*16 + 4*kt];
                bf[nj][0] = u.x;
                bf[nj][1] = u.y;
            }
            #pragma unroll
            for (int mi = 0; mi < 4; mi++)
                #pragma unroll
                for (int nj = 0; nj < 4; nj++)
                    mma16(acc[mi][nj], af[mi], bf[nj]);
        }
        __syncthreads();
    }

    #pragma unroll
    for (int mi = 0; mi < 4; mi++)
        #pragma unroll
        for (int nj = 0; nj < 4; nj++)
            #pragma unroll
            for (int r = 0; r < 4; r++) {
                int gm = rowBase + wm + mi*16 + g + (r>>1)*8;
                int gn = wn + nj*8 + kt*2 + (r&1);
                float v = acc[mi][nj][r];
                if (MODE == 0) {
                    int b = gm / FN, j = gm - b*FN;
                    g_hh[((size_t)b*CCH + gn)*AP + ilv16(j)] = __float2half_rn(v);
                } else if (MODE == 1) {
                    if (gm < M) {
                        __half* dst = Cg + ((size_t)blockIdx.y*FN + gm)*CCH;
                        dst[ilv16(gn)] = __float2half_rn(fast_tanh(v + __ldg(bias + gn)));
                    }
                } else {
                    atomicAdd(&Cf[(size_t)gm*H1 + bOff + gn], v);
                }
            }
}

// ---------------- legacy tf32 mma.sync GEMM (small MLP layers) ----------------
__global__ __launch_bounds__(256)
void mmak(const float* __restrict__ A, const float* __restrict__ Bm,
          float* __restrict__ C, int M, int N, int K)
{
    __shared__ uint32_t As[2][16][PADK];
    __shared__ uint32_t Bs[2][16][PADK];
    const int tid = threadIdx.x, lane = tid & 31, w = tid >> 5;
    const int wm = (w & 1)*64, wn = (w >> 1)*32;
    const int g = lane >> 2, kt = lane & 3;
    const int rowBase = blockIdx.x*128, colBase = blockIdx.y*128;
    const int aRow = tid >> 1, aCol = (tid & 1)*8;
    const int bRow = tid >> 4, bCol = (tid & 15)*8;
    float acc[4][4][4];
    #pragma unroll
    for (int mi = 0; mi < 4; mi++)
        #pragma unroll
        for (int nj = 0; nj < 4; nj++)
            #pragma unroll
            for (int r = 0; r < 4; r++) acc[mi][nj][r] = 0.f;
    const int gmA = rowBase + aRow;
    float4 pa[2], pb[2];
    auto loadT = [&](int k0) {
        #pragma unroll
        for (int h = 0; h < 2; h++) {
            int gk = k0 + aCol + h*4;
            float4 v = make_float4(0.f,0.f,0.f,0.f);
            if (gmA < M && gk + 3 < K) v = *(const float4*)(A + (size_t)gmA*K + gk);
            pa[h] = v;
        }
        int gk = k0 + bRow;
        #pragma unroll
        for (int h = 0; h < 2; h++) {
            int gn = colBase + bCol + h*4;
            float4 v = make_float4(0.f,0.f,0.f,0.f);
            if (gk < K && gn < N) v = *(const float4*)(Bm + (size_t)gk*N + gn);
            pb[h] = v;
        }
    };
    auto storeT = [&](int buf) {
        #pragma unroll
        for (int h = 0; h < 2; h++) {
            As[buf][aCol+h*4+0][aRow] = f2tf(pa[h].x);
            As[buf][aCol+h*4+1][aRow] = f2tf(pa[h].y);
            As[buf][aCol+h*4+2][aRow] = f2tf(pa[h].z);
            As[buf][aCol+h*4+3][aRow] = f2tf(pa[h].w);
            Bs[buf][bRow][bCol+h*4+0] = f2tf(pb[h].x);
            Bs[buf][bRow][bCol+h*4+1] = f2tf(pb[h].y);
            Bs[buf][bRow][bCol+h*4+2] = f2tf(pb[h].z);
            Bs[buf][bRow][bCol+h*4+3] = f2tf(pb[h].w);
        }
    };
    auto comp = [&](int buf) {
        #pragma unroll
        for (int ks = 0; ks < 2; ks++) {
            uint32_t af[4][4], bf[4][2];
            #pragma unroll
            for (int mi = 0; mi < 4; mi++) {
                int m = wm + mi*16;
                af[mi][0] = As[buf][ks*8+kt  ][m+g  ];
                af[mi][1] = As[buf][ks*8+kt  ][m+g+8];
                af[mi][2] = As[buf][ks*8+kt+4][m+g  ];
                af[mi][3] = As[buf][ks*8+kt+4][m+g+8];
            }
            #pragma unroll
            for (int nj = 0; nj < 4; nj++) {
                int n = wn + nj*8;
                bf[nj][0] = Bs[buf][ks*8+kt  ][n+g];
                bf[nj][1] = Bs[buf][ks*8+kt+4][n+g];
            }
            #pragma unroll
            for (int mi = 0; mi < 4; mi++)
                #pragma unroll
                for (int nj = 0; nj < 4; nj++) mma8(acc[mi][nj], af[mi], bf[nj]);
        }
    };
    const int nIter = (K + 15) >> 4;
    loadT(0); storeT(0); __syncthreads();
    for (int t = 1; t < nIter; t++) {
        loadT(t*16);
        comp((t-1) & 1);
        storeT(t & 1);
        __syncthreads();
    }
    comp((nIter-1) & 1);
    #pragma unroll
    for (int mi = 0; mi < 4; mi++)
        #pragma unroll
        for (int nj = 0; nj < 4; nj++)
            #pragma unroll
            for (int r = 0; r < 4; r++) {
                int gm = rowBase + wm + mi*16 + g + (r>>1)*8;
                int gn = colBase + wn + nj*8 + kt*2 + (r&1);
                if (gm < M && gn < N) C[(size_t)gm*N + gn] = acc[mi][nj][r];
            }
}

// ---------------- BN / pool / head ----------------
__global__ void k_x0_bn(const float* __restrict__ x, const float* __restrict__ g,
                        const float* __restrict__ be, __half* __restrict__ z)
{
    int r = blockIdx.x;
    int c = r + threadIdx.x;
    if (c >= FN) return;
    long j = (long)r*FN - (long)r*(r-1)/2 + (c - r);
    long zi = (j & ~15L) + pl16((int)(j & 15));
    float s = 0.f, ss = 0.f;
    for (int b = 0; b < BGRAPH; b++) {
        float v = x[((size_t)(b*FN + r))*FN + c];
        s += v; ss += v*v;
    }
    float m = s*(1.f/BGRAPH);
    float var = ss*(1.f/BGRAPH) - m*m;
    float sc = rsqrtf(var + EPSV)*g[j];
    float bb = be[j];
    for (int b = 0; b < BGRAPH; b++) {
        float v = x[((size_t)(b*FN + r))*FN + c];
        z[(size_t)b*ZP + zi] = __float2half_rn((v - m)*sc + bb);
    }
}
__global__ void k_pool(const __half* __restrict__ x1, const __half* __restrict__ x2,
                       const __half* __restrict__ x3, float* __restrict__ hp)
{
    int b = blockIdx.x, l = blockIdx.y, k = threadIdx.x;
    const __half* base = (l==0 ? x1 : l==1 ? x2 : x3) + (size_t)b*FN*CCH + k;
    float s0=0.f, s1=0.f, s2=0.f, s3=0.f;
    #pragma unroll 1
    for (int n = 0; n < FN; n += 4) {
        s0 += __half2float(base[(size_t)(n+0)*CCH]);
        s1 += __half2float(base[(size_t)(n+1)*CCH]);
        s2 += __half2float(base[(size_t)(n+2)*CCH]);
        s3 += __half2float(base[(size_t)(n+3)*CCH]);
    }
    int oc = (k & ~15) + orig16p(k & 15);
    hp[b*384 + l*CCH + oc] = (s0+s1+s2+s3)*(1.0f/FN);
}
__global__ void k_bn_pool(const float* __restrict__ hp, const float* __restrict__ g,
                          const float* __restrict__ be, __half* __restrict__ z)
{
    int j = blockIdx.x*blockDim.x + threadIdx.x;
    if (j >= ZP - TRI) return;
    long cg2 = (long)TRI + j;
    long zi = (cg2 & ~15L) + pl16((int)(cg2 & 15));
    if (j >= 384) {
        for (int b = 0; b < BGRAPH; b++) z[(size_t)b*ZP + zi] = __half(0.f);
        return;
    }
    float s = 0.f, ss = 0.f;
    for (int b = 0; b < BGRAPH; b++) { float v = hp[b*384 + j]; s += v; ss += v*v; }
    float m = s*(1.f/BGRAPH);
    float var = ss*(1.f/BGRAPH) - m*m;
    float sc = rsqrtf(var + EPSV)*g[j];
    float bb = be[j];
    for (int b = 0; b < BGRAPH; b++)
        z[(size_t)b*ZP + zi] = __float2half_rn((hp[b*384 + j] - m)*sc + bb);
}
__global__ void k_bn_relu(const float* __restrict__ X, const float* __restrict__ bias,
                          const float* __restrict__ gam, const float* __restrict__ bet,
                          float* __restrict__ Y, int ncols)
{
    int col = blockIdx.x, t = threadIdx.x;
    float v = X[t*ncols + col] + bias[col];
    float s = v, ss = v*v;
    #pragma unroll
    for (int o = 16; o > 0; o >>= 1) {
        s  += __shfl_down_sync(0xffffffffu, s,  o);
        ss += __shfl_down_sync(0xffffffffu, ss, o);
    }
    __shared__ float ws[4], wss[4];
    __shared__ float sm, sscale;
    int wid = t >> 5, lane = t & 31;
    if (lane == 0) { ws[wid] = s; wss[wid] = ss; }
    __syncthreads();
    if (t == 0) {
        float S = ws[0]+ws[1]+ws[2]+ws[3];
        float SS = wss[0]+wss[1]+wss[2]+wss[3];
        float m = S*(1.f/BGRAPH);
        sm = m; sscale = rsqrtf(SS*(1.f/BGRAPH) - m*m + EPSV);
    }
    __syncthreads();
    float o = (v - sm)*sscale*gam[col] + bet[col];
    Y[t*ncols + col] = fmaxf(o, 0.f);
}
__global__ void k_head(const float* __restrict__ a3, const float* __restrict__ W4,
                       const float* __restrict__ b4, float* __restrict__ out)
{
    int b = blockIdx.x, lane = threadIdx.x;
    float s0 = 0.f, s1 = 0.f;
    for (int i = lane; i < H2; i += 32) {
        float v = a3[b*H2 + i];
        s0 = fmaf(v, W4[i*2+0], s0);
        s1 = fmaf(v, W4[i*2+1], s1);
    }
    #pragma unroll
    for (int o = 16; o > 0; o >>= 1) {
        s0 += __shfl_down_sync(0xffffffffu, s0, o);
        s1 += __shfl_down_sync(0xffffffffu, s1, o);
    }
    if (lane == 0) {
        float l0 = s0 + b4[0], l1 = s1 + b4[1];
        float m = fmaxf(l0, l1);
        float lse = m + logf(expf(l0-m) + expf(l1-m));
        out[b*2+0] = l0 - lse;
        out[b*2+1] = l1 - lse;
    }
}

// ---------------- launch ----------------
extern "C" void kernel_launch(void* const* d_in, const int* in_sizes, int n_in,
                              void* d_out, int out_size)
{
    const float* x    = (const float*)d_in[0];
    const int*   esrc = (const int*)d_in[1];
    const int*   edst = (const int*)d_in[2];
    const float* Wc1  = (const float*)d_in[4];
    const float* bc1  = (const float*)d_in[5];
    const float* Wc2  = (const float*)d_in[6];
    const float* bc2  = (const float*)d_in[7];
    const float* Wc3  = (const float*)d_in[8];
    const float* bc3  = (const float*)d_in[9];
    const float* bn_g = (const float*)d_in[10];
    const float* bn_b = (const float*)d_in[11];
    const float* bnh_g= (const float*)d_in[12];
    const float* bnh_b= (const float*)d_in[13];
    const float* W1   = (const float*)d_in[14];
    const float* b1   = (const float*)d_in[15];
    const float* g1   = (const float*)d_in[16];
    const float* be1  = (const float*)d_in[17];
    const float* W2   = (const float*)d_in[18];
    const float* b2   = (const float*)d_in[19];
    const float* g2   = (const float*)d_in[20];
    const float* be2  = (const float*)d_in[21];
    const float* W3   = (const float*)d_in[22];
    const float* b3   = (const float*)d_in[23];
    const float* g3   = (const float*)d_in[24];
    const float* be3  = (const float*)d_in[25];
    const float* W4   = (const float*)d_in[26];
    const float* b4   = (const float*)d_in[27];
    float* out = (float*)d_out;

    const int DSMH = 3*12288*2;   // 73728 B (fp16 GEMM, BK=32, 3 stages)
    cudaFuncSetAttribute(gkh<0>, cudaFuncAttributeMaxDynamicSharedMemorySize, DSMH);
    cudaFuncSetAttribute(gkh<1>, cudaFuncAttributeMaxDynamicSharedMemorySize, DSMH);
    cudaFuncSetAttribute(gkh<2>, cudaFuncAttributeMaxDynamicSharedMemorySize, DSMH);

    void *pDinv, *pAh, *pXh, *pHh, *pX1, *pX2, *pX3, *pZh, *pW1h, *pHp, *pA1, *pA2, *pA3, *pWh;
    cudaGetSymbolAddress(&pDinv, g_dinv);
    cudaGetSymbolAddress(&pAh,  g_Ah);
    cudaGetSymbolAddress(&pXh,  g_xh);
    cudaGetSymbolAddress(&pHh,  g_hh);
    cudaGetSymbolAddress(&pX1,  g_x1h);
    cudaGetSymbolAddress(&pX2,  g_x2h);
    cudaGetSymbolAddress(&pX3,  g_x3h);
    cudaGetSymbolAddress(&pZh,  g_zh);
    cudaGetSymbolAddress(&pW1h, g_w1h);
    cudaGetSymbolAddress(&pHp,  g_hpool);
    cudaGetSymbolAddress(&pA1,  g_a1);
    cudaGetSymbolAddress(&pA2,  g_a2);
    cudaGetSymbolAddress(&pA3,  g_a3);
    cudaGetSymbolAddress(&pWh,  g_wh);

    const __half* wh = (const __half*)pWh;
    const __half* xh = (const __half*)pXh;
    const __half* Ah = (const __half*)pAh;
    const __half* hh = (const __half*)pHh;
    const __half* zh = (const __half*)pZh;
    const __half* w1h = (const __half*)pW1h;

    // launch order: first fp16 GEMM at index 6 (ncu capture slot)
    cudaMemsetAsync(pHh, 0, (size_t)BGRAPH*CCH*AP*2, 0);             // 0
    cudaMemsetAsync(pDinv, 0, (size_t)NNODE*4, 0);                   // 1
    cudaMemsetAsync(pAh, 0, (size_t)BGRAPH*AP*AP*2, 0);              // 2
    k_count_deg<<<(NEDGE+255)/256, 256>>>(edst);                     // 3
    k_prep<<<(3*CCH*(AP/16)+255)/256, 256>>>(Wc1, Wc2, Wc3);         // 4
    k_xh<<<(NNODE*(AP/16)+255)/256, 256>>>(x);                       // 5
    gkh<0><<<dim3(360,1), 256, DSMH>>>(xh, wh, nullptr, nullptr, nullptr,  // 6 <- ncu
                                       AP, AP, NNODE, AP);
    k_make_dinv<<<(NNODE+255)/256, 256>>>();                         // 7
    k_build<<<(NEDGE+NNODE+255)/256, 256>>>(esrc, edst);             // 8
    k_w1h<<<(H1*(ZP/16)+255)/256, 256>>>(W1);                        // 9

    gkh<1><<<dim3(3,BGRAPH), 256, DSMH>>>(Ah, hh, bc1, (__half*)pX1, nullptr, AP, AP, FN, AP);
    gkh<0><<<dim3(360,1), 256, DSMH>>>((const __half*)pX1, wh + (size_t)CCH*AP, nullptr, nullptr,
                                       nullptr, CCH, AP, NNODE, CCH);
    gkh<1><<<dim3(3,BGRAPH), 256, DSMH>>>(Ah, hh, bc2, (__half*)pX2, nullptr, AP, AP, FN, AP);
    gkh<0><<<dim3(360,1), 256, DSMH>>>((const __half*)pX2, wh + (size_t)2*CCH*AP, nullptr, nullptr,
                                       nullptr, CCH, AP, NNODE, CCH);
    gkh<1><<<dim3(3,BGRAPH), 256, DSMH>>>(Ah, hh, bc3, (__half*)pX3, nullptr, AP, AP, FN, AP);

    // features
    k_x0_bn<<<FN, 384>>>(x, bn_g, bn_b, (__half*)pZh);
    k_pool<<<dim3(BGRAPH,3), CCH>>>((const __half*)pX1, (const __half*)pX2,
                                    (const __half*)pX3, (float*)pHp);
    k_bn_pool<<<1, 1024>>>((const float*)pHp, bnh_g, bnh_b, (__half*)pZh);

    // MLP head: zW1 fp16 split-K, then tf32 small layers
    cudaMemsetAsync(pA1, 0, (size_t)BGRAPH*H1*4, 0);
    gkh<2><<<dim3(1,4,64), 256, DSMH>>>(zh, w1h, nullptr, nullptr, (float*)pA1,
                                        ZP, ZP, BGRAPH, 1024);
    k_bn_relu<<<H1, 128>>>((const float*)pA1, b1, g1, be1, (float*)pA1, H1);
    mmak<<<dim3(1,2), 256>>>((const float*)pA1, W2, (float*)pA2, BGRAPH, H2, H1);
    k_bn_relu<<<H2, 128>>>((const float*)pA2, b2, g2, be2, (float*)pA2, H2);
    mmak<<<dim3(1,2), 256>>>((const float*)pA2, W3, (float*)pA3, BGRAPH, H2, H2);
    k_bn_relu<<<H2, 128>>>((const float*)pA3, b3, g3, be3, (float*)pA3, H2);
    k_head<<<BGRAPH, 32>>>((const float*)pA3, W4, b4, out);
}

// round 13
// speedup vs baseline: 1.0444x; 1.0026x over previous
#include <cuda_runtime.h>
#include <cuda_fp16.h>
#include <math.h>
#include <stdint.h>

#define FN 360
#define BGRAPH 128
#define NNODE (FN*BGRAPH)
#define NEDGE 1000000
#define CCH 128
#define TRI 64980
#define D1 65364
#define ZP 65536
#define H1 512
#define H2 256
#define EPSV 1e-5f
#define PADK 136
#define AP 384

// ---------------- scratch ----------------
__device__ __align__(16) float  g_dinv[NNODE];
__device__ __align__(16) __half g_Ah[(size_t)BGRAPH*AP*AP];   // fp16 adjacency, ilv16 k
__device__ __align__(16) __half g_xh[(size_t)NNODE*AP];       // fp16 x, ilv16 k
__device__ __align__(16) __half g_wh[(size_t)3*CCH*AP];       // fp16 W^T, ilv16 k
__device__ __align__(16) __half g_hh[(size_t)BGRAPH*CCH*AP];  // fp16 h^T [b][c][j ilv16]
__device__ __align__(16) __half g_x1h[(size_t)NNODE*CCH];
__device__ __align__(16) __half g_x2h[(size_t)NNODE*CCH];
__device__ __align__(16) __half g_x3h[(size_t)NNODE*CCH];
__device__ __align__(16) __half g_zh[(size_t)BGRAPH*ZP];      // fp16 z, ilv16 cols
__device__ __align__(16) __half g_w1h[(size_t)H1*ZP];         // fp16 W1^T [n][k ilv16]
__device__ __align__(16) float  g_hpool[BGRAPH*384];
__device__ __align__(16) float  g_a1[BGRAPH*H1];
__device__ __align__(16) float  g_a2[BGRAPH*H2];
__device__ __align__(16) float  g_a3[BGRAPH*H2];

// ---------------- helpers ----------------
__device__ __forceinline__ uint32_t f2tf(float f) {
    uint32_t u; asm("cvt.rna.tf32.f32 %0, %1;" : "=r"(u) : "f"(f)); return u;
}
// fp16 ilv16: halfs at pos 4kt..4kt+3 hold k = {2kt,2kt+1,2kt+8,2kt+9}
__device__ __forceinline__ int pl16(int j)  { int p=j>>1, b=j&1; return ((p&3)<<2)|(((p>>2)&1)<<1)|b; }
__device__ __forceinline__ int ilv16(int c) { return (c & ~15) + pl16(c & 15); }
__device__ __forceinline__ int orig16p(int q){ int b=q&1, t=(q>>1)&7; int p=((t&1)<<2)|(t>>1); return 2*p+b; }
__device__ __forceinline__ float fast_tanh(float x) {
    float e = __expf(2.0f*x);
    return 1.0f - __fdividef(2.0f, e + 1.0f);
}
__device__ __forceinline__ uint32_t s2u(const void* p) {
    uint32_t a;
    asm("{ .reg .u64 t; cvta.to.shared.u64 t, %1; cvt.u32.u64 %0, t; }" : "=r"(a) : "l"(p));
    return a;
}
__device__ __forceinline__ void cpa16(uint32_t d, const void* g) {
    asm volatile("cp.async.cg.shared.global [%0], [%1], 16;" :: "r"(d), "l"(g));
}
__device__ __forceinline__ void mma8(float* c, const uint32_t* a, const uint32_t* b) {
    asm volatile("mma.sync.aligned.m16n8k8.row.col.f32.tf32.tf32.f32 "
        "{%0,%1,%2,%3}, {%4,%5,%6,%7}, {%8,%9}, {%0,%1,%2,%3};"
        : "+f"(c[0]), "+f"(c[1]), "+f"(c[2]), "+f"(c[3])
        : "r"(a[0]), "r"(a[1]), "r"(a[2]), "r"(a[3]), "r"(b[0]), "r"(b[1]));
}
__device__ __forceinline__ void mma16(float* c, const uint32_t* a, const uint32_t* b) {
    asm volatile("mma.sync.aligned.m16n8k16.row.col.f32.f16.f16.f32 "
        "{%0,%1,%2,%3}, {%4,%5,%6,%7}, {%8,%9}, {%0,%1,%2,%3};"
        : "+f"(c[0]), "+f"(c[1]), "+f"(c[2]), "+f"(c[3])
        : "r"(a[0]), "r"(a[1]), "r"(a[2]), "r"(a[3]), "r"(b[0]), "r"(b[1]));
}

// ---------------- prep ----------------
__global__ void k_prep(const float* __restrict__ Wc1, const float* __restrict__ Wc2,
                       const float* __restrict__ Wc3) {
    int i = blockIdx.x*blockDim.x + threadIdx.x;
    if (i >= 3*CCH*(AP/16)) return;
    int w = i / (CCH*(AP/16));
    int r = (i / (AP/16)) % CCH;
    int grp = i % (AP/16);
    const float* W = (w==0) ? Wc1 : (w==1) ? Wc2 : Wc3;
    int KW = (w==0) ? FN : CCH;
    __align__(16) __half o[16];
    #pragma unroll
    for (int j = 0; j < 16; j++) {
        int k = grp*16 + j;
        o[pl16(j)] = (k < KW) ? __float2half_rn(W[k*CCH + r]) : __half(0.f);
    }
    __half* dst = g_wh + ((size_t)(w*CCH + r))*AP + grp*16;
    ((uint4*)dst)[0] = ((uint4*)o)[0];
    ((uint4*)dst)[1] = ((uint4*)o)[1];
}
__global__ void k_xh(const float* __restrict__ x) {
    int i = blockIdx.x*blockDim.x + threadIdx.x;
    if (i >= NNODE*(AP/16)) return;
    int n = i / (AP/16), grp = i % (AP/16);
    __align__(16) __half o[16];
    #pragma unroll
    for (int j = 0; j < 16; j++) {
        int k = grp*16 + j;
        o[pl16(j)] = (k < FN) ? __float2half_rn(x[(size_t)n*FN + k]) : __half(0.f);
    }
    __half* dst = g_xh + (size_t)n*AP + grp*16;
    ((uint4*)dst)[0] = ((uint4*)o)[0];
    ((uint4*)dst)[1] = ((uint4*)o)[1];
}
// W1 [D1][H1] fp32 -> g_w1h [H1][ZP] fp16, k interleaved; zeros for k >= D1
__global__ void k_w1h(const float* __restrict__ W1) {
    int i = blockIdx.x*blockDim.x + threadIdx.x;
    if (i >= H1*(ZP/16)) return;
    int n = i & (H1-1);
    int grp = i >> 9;
    __align__(16) __half o[16];
    #pragma unroll
    for (int j = 0; j < 16; j++) {
        int k = grp*16 + j;
        o[pl16(j)] = (k < D1) ? __float2half_rn(W1[(size_t)k*H1 + n]) : __half(0.f);
    }
    __half* dst = g_w1h + (size_t)n*ZP + grp*16;
    ((uint4*)dst)[0] = ((uint4*)o)[0];
    ((uint4*)dst)[1] = ((uint4*)o)[1];
}
__global__ void k_count_deg(const int* __restrict__ dst) {
    int i = blockIdx.x*blockDim.x + threadIdx.x;
    if (i < NEDGE) atomicAdd(&g_dinv[dst[i]], 1.0f);
}
__global__ void k_make_dinv() {
    int i = blockIdx.x*blockDim.x + threadIdx.x;
    if (i < NNODE) g_dinv[i] = rsqrtf(g_dinv[i] + 1.0f);
}
// build adjacency directly in fp16 (ilv16 columns); g_Ah pre-zeroed
__global__ void k_build(const int* __restrict__ src, const int* __restrict__ dst) {
    int i = blockIdx.x*blockDim.x + threadIdx.x;
    if (i < NEDGE) {
        int d = dst[i], s = src[i];
        int b = d / FN, r = d - b*FN, c = s - b*FN;
        atomicAdd(&g_Ah[((size_t)b*AP + r)*AP + ilv16(c)],
                  __float2half_rn(g_dinv[s]*g_dinv[d]));
    } else if (i < NEDGE + NNODE) {
        int n = i - NEDGE, b = n / FN, r = n - b*FN;
        atomicAdd(&g_Ah[((size_t)b*AP + r)*AP + ilv16(r)],
                  __float2half_rn(g_dinv[n]*g_dinv[n]));
    }
}

// ---------------- fp16 HMMA GEMM, 64x128 tile, BK=32, 3-stage cp.async -------
// 256 thr, 8 warps (2 m x 4 n), warp tile 32x32. A [m][k ilv16], B [n][k ilv16].
// MODE 0: XW -> g_hh[(b*CCH+c)*AP + ilv16(j)]. grid(720)
// MODE 1: AH -> xs fp16 = tanh(D+bias). grid(6, BGRAPH), y = graph
// MODE 2: zW1 split-K: grid(2, H1/128, 64); kbeg = z*1024; B rows = y*128 + n;
//         fp32 atomicAdd into Cf. All pads zeroed.
template<int MODE>
__global__ __launch_bounds__(256, 3)
void gkh(const __half* __restrict__ Ag, const __half* __restrict__ Bg,
         const float* __restrict__ bias, __half* __restrict__ Cg,
         float* __restrict__ Cf, int lda, int ldb, int M, int K)
{
    extern __shared__ __align__(16) __half dynh[];
    const int STG = 9216;                  // halfs/stage: A 64x48 + B 128x48
    const int tid = threadIdx.x, lane = tid & 31, w = tid >> 5;
    const int wm = (w & 1)*32, wn = (w >> 1)*32;
    const int g = lane >> 2, kt = lane & 3;
    const int rowBase = blockIdx.x*64;
    const int bOff = (MODE == 2) ? blockIdx.y*128 : 0;

    if (MODE == 1) {
        Ag += (size_t)blockIdx.y * AP * AP;
        Bg += (size_t)blockIdx.y * CCH * AP;
    }
    const int kbeg = (MODE == 2) ? blockIdx.z*1024 : 0;
    const int am = tid >> 2;               // A row 0..63, 4 threads/row
    const int ak = (tid & 3) * 8;          // 8-half chunk
    const int bm = tid >> 1;               // B row 0..127, 2 threads/row
    const int bk = (tid & 1) * 16;         // 16-half block

    auto load_chunk = [&](int c, int stg) {
        int k0 = kbeg + c*32;
        __half* As = dynh + stg*STG;
        __half* Bs = As + 3072;
        const __half* ar = Ag + (size_t)(rowBase + am)*lda + k0 + ak;
        cpa16(s2u(As + am*48 + ak), ar);
        const __half* br = Bg + (size_t)(bOff + bm)*ldb + k0 + bk;
        uint32_t bd = s2u(Bs + bm*48 + bk);
        cpa16(bd,      br);
        cpa16(bd + 16, br + 8);
        asm volatile("cp.async.commit_group;" ::: "memory");
    };

    float acc[2][4][4];
    #pragma unroll
    for (int mi = 0; mi < 2; mi++)
        #pragma unroll
        for (int nj = 0; nj < 4; nj++)
            #pragma unroll
            for (int r = 0; r < 4; r++) acc[mi][nj][r] = 0.f;

    const int nch = K >> 5;
    load_chunk(0, 0);
    load_chunk(1, 1);
    for (int c = 0; c < nch; c++) {
        int buf = c % 3;
        if (c + 2 < nch) {
            load_chunk(c + 2, (c + 2) % 3);
            asm volatile("cp.async.wait_group 2;" ::: "memory");
        } else if (c + 1 < nch) {
            asm volatile("cp.async.wait_group 1;" ::: "memory");
        } else {
            asm volatile("cp.async.wait_group 0;" ::: "memory");
        }
        __syncthreads();
        const __half* As = dynh + buf*STG;
        const __half* Bs = As + 3072;
        #pragma unroll
        for (int ks = 0; ks < 2; ks++) {
            uint32_t af[2][4], bf[4][2];
            #pragma unroll
            for (int mi = 0; mi < 2; mi++) {
                int m = wm + mi*16 + g;
                uint2 va = *(const uint2*)&As[m*48     + ks*16 + 4*kt];
                uint2 vb = *(const uint2*)&As[(m+8)*48 + ks*16 + 4*kt];
                af[mi][0] = va.x;
                af[mi][1] = vb.x;
                af[mi][2] = va.y;
                af[mi][3] = vb.y;
            }
            #pragma unroll
            for (int nj = 0; nj < 4; nj++) {
                int n = wn + nj*8 + g;
                uint2 u = *(const uint2*)&Bs[n*48 + ks*16 + 4*kt];
                bf[nj][0] = u.x;
                bf[nj][1] = u.y;
            }
            #pragma unroll
            for (int mi = 0; mi < 2; mi++)
                #pragma unroll
                for (int nj = 0; nj < 4; nj++)
                    mma16(acc[mi][nj], af[mi], bf[nj]);
        }
        __syncthreads();
    }

    #pragma unroll
    for (int mi = 0; mi < 2; mi++)
        #pragma unroll
        for (int nj = 0; nj < 4; nj++)
            #pragma unroll
            for (int r = 0; r < 4; r++) {
                int gm = rowBase + wm + mi*16 + g + (r>>1)*8;
                int gn = wn + nj*8 + kt*2 + (r&1);
                float v = acc[mi][nj][r];
                if (MODE == 0) {
                    int b = gm / FN, j = gm - b*FN;
                    g_hh[((size_t)b*CCH + gn)*AP + ilv16(j)] = __float2half_rn(v);
                } else if (MODE == 1) {
                    if (gm < M) {
                        __half* dst = Cg + ((size_t)blockIdx.y*FN + gm)*CCH;
                        dst[ilv16(gn)] = __float2half_rn(fast_tanh(v + __ldg(bias + gn)));
                    }
                } else {
                    atomicAdd(&Cf[(size_t)gm*H1 + bOff + gn], v);
                }
            }
}

// ---------------- legacy tf32 mma.sync GEMM (small MLP layers) ----------------
__global__ __launch_bounds__(256)
void mmak(const float* __restrict__ A, const float* __restrict__ Bm,
          float* __restrict__ C, int M, int N, int K)
{
    __shared__ uint32_t As[2][16][PADK];
    __shared__ uint32_t Bs[2][16][PADK];
    const int tid = threadIdx.x, lane = tid & 31, w = tid >> 5;
    const int wm = (w & 1)*64, wn = (w >> 1)*32;
    const int g = lane >> 2, kt = lane & 3;
    const int rowBase = blockIdx.x*128, colBase = blockIdx.y*128;
    const int aRow = tid >> 1, aCol = (tid & 1)*8;
    const int bRow = tid >> 4, bCol = (tid & 15)*8;
    float acc[4][4][4];
    #pragma unroll
    for (int mi = 0; mi < 4; mi++)
        #pragma unroll
        for (int nj = 0; nj < 4; nj++)
            #pragma unroll
            for (int r = 0; r < 4; r++) acc[mi][nj][r] = 0.f;
    const int gmA = rowBase + aRow;
    float4 pa[2], pb[2];
    auto loadT = [&](int k0) {
        #pragma unroll
        for (int h = 0; h < 2; h++) {
            int gk = k0 + aCol + h*4;
            float4 v = make_float4(0.f,0.f,0.f,0.f);
            if (gmA < M && gk + 3 < K) v = *(const float4*)(A + (size_t)gmA*K + gk);
            pa[h] = v;
        }
        int gk = k0 + bRow;
        #pragma unroll
        for (int h = 0; h < 2; h++) {
            int gn = colBase + bCol + h*4;
            float4 v = make_float4(0.f,0.f,0.f,0.f);
            if (gk < K && gn < N) v = *(const float4*)(Bm + (size_t)gk*N + gn);
            pb[h] = v;
        }
    };
    auto storeT = [&](int buf) {
        #pragma unroll
        for (int h = 0; h < 2; h++) {
            As[buf][aCol+h*4+0][aRow] = f2tf(pa[h].x);
            As[buf][aCol+h*4+1][aRow] = f2tf(pa[h].y);
            As[buf][aCol+h*4+2][aRow] = f2tf(pa[h].z);
            As[buf][aCol+h*4+3][aRow] = f2tf(pa[h].w);
            Bs[buf][bRow][bCol+h*4+0] = f2tf(pb[h].x);
            Bs[buf][bRow][bCol+h*4+1] = f2tf(pb[h].y);
            Bs[buf][bRow][bCol+h*4+2] = f2tf(pb[h].z);
            Bs[buf][bRow][bCol+h*4+3] = f2tf(pb[h].w);
        }
    };
    auto comp = [&](int buf) {
        #pragma unroll
        for (int ks = 0; ks < 2; ks++) {
            uint32_t af[4][4], bf[4][2];
            #pragma unroll
            for (int mi = 0; mi < 4; mi++) {
                int m = wm + mi*16;
                af[mi][0] = As[buf][ks*8+kt  ][m+g  ];
                af[mi][1] = As[buf][ks*8+kt  ][m+g+8];
                af[mi][2] = As[buf][ks*8+kt+4][m+g  ];
                af[mi][3] = As[buf][ks*8+kt+4][m+g+8];
            }
            #pragma unroll
            for (int nj = 0; nj < 4; nj++) {
                int n = wn + nj*8;
                bf[nj][0] = Bs[buf][ks*8+kt  ][n+g];
                bf[nj][1] = Bs[buf][ks*8+kt+4][n+g];
            }
            #pragma unroll
            for (int mi = 0; mi < 4; mi++)
                #pragma unroll
                for (int nj = 0; nj < 4; nj++) mma8(acc[mi][nj], af[mi], bf[nj]);
        }
    };
    const int nIter = (K + 15) >> 4;
    loadT(0); storeT(0); __syncthreads();
    for (int t = 1; t < nIter; t++) {
        loadT(t*16);
        comp((t-1) & 1);
        storeT(t & 1);
        __syncthreads();
    }
    comp((nIter-1) & 1);
    #pragma unroll
    for (int mi = 0; mi < 4; mi++)
        #pragma unroll
        for (int nj = 0; nj < 4; nj++)
            #pragma unroll
            for (int r = 0; r < 4; r++) {
                int gm = rowBase + wm + mi*16 + g + (r>>1)*8;
                int gn = colBase + wn + nj*8 + kt*2 + (r&1);
                if (gm < M && gn < N) C[(size_t)gm*N + gn] = acc[mi][nj][r];
            }
}

// ---------------- BN / pool / head ----------------
__global__ void k_x0_bn(const float* __restrict__ x, const float* __restrict__ g,
                        const float* __restrict__ be, __half* __restrict__ z)
{
    int r = blockIdx.x;
    int c = r + threadIdx.x;
    if (c >= FN) return;
    long j = (long)r*FN - (long)r*(r-1)/2 + (c - r);
    long zi = (j & ~15L) + pl16((int)(j & 15));
    float s = 0.f, ss = 0.f;
    for (int b = 0; b < BGRAPH; b++) {
        float v = x[((size_t)(b*FN + r))*FN + c];
        s += v; ss += v*v;
    }
    float m = s*(1.f/BGRAPH);
    float var = ss*(1.f/BGRAPH) - m*m;
    float sc = rsqrtf(var + EPSV)*g[j];
    float bb = be[j];
    for (int b = 0; b < BGRAPH; b++) {
        float v = x[((size_t)(b*FN + r))*FN + c];
        z[(size_t)b*ZP + zi] = __float2half_rn((v - m)*sc + bb);
    }
}
__global__ void k_pool(const __half* __restrict__ x1, const __half* __restrict__ x2,
                       const __half* __restrict__ x3, float* __restrict__ hp)
{
    int b = blockIdx.x, l = blockIdx.y, k = threadIdx.x;
    const __half* base = (l==0 ? x1 : l==1 ? x2 : x3) + (size_t)b*FN*CCH + k;
    float s0=0.f, s1=0.f, s2=0.f, s3=0.f;
    #pragma unroll 1
    for (int n = 0; n < FN; n += 4) {
        s0 += __half2float(base[(size_t)(n+0)*CCH]);
        s1 += __half2float(base[(size_t)(n+1)*CCH]);
        s2 += __half2float(base[(size_t)(n+2)*CCH]);
        s3 += __half2float(base[(size_t)(n+3)*CCH]);
    }
    int oc = (k & ~15) + orig16p(k & 15);
    hp[b*384 + l*CCH + oc] = (s0+s1+s2+s3)*(1.0f/FN);
}
__global__ void k_bn_pool(const float* __restrict__ hp, const float* __restrict__ g,
                          const float* __restrict__ be, __half* __restrict__ z)
{
    int j = blockIdx.x*blockDim.x + threadIdx.x;
    if (j >= ZP - TRI) return;
    long cg2 = (long)TRI + j;
    long zi = (cg2 & ~15L) + pl16((int)(cg2 & 15));
    if (j >= 384) {
        for (int b = 0; b < BGRAPH; b++) z[(size_t)b*ZP + zi] = __half(0.f);
        return;
    }
    float s = 0.f, ss = 0.f;
    for (int b = 0; b < BGRAPH; b++) { float v = hp[b*384 + j]; s += v; ss += v*v; }
    float m = s*(1.f/BGRAPH);
    float var = ss*(1.f/BGRAPH) - m*m;
    float sc = rsqrtf(var + EPSV)*g[j];
    float bb = be[j];
    for (int b = 0; b < BGRAPH; b++)
        z[(size_t)b*ZP + zi] = __float2half_rn((hp[b*384 + j] - m)*sc + bb);
}
__global__ void k_bn_relu(const float* __restrict__ X, const float* __restrict__ bias,
                          const float* __restrict__ gam, const float* __restrict__ bet,
                          float* __restrict__ Y, int ncols)
{
    int col = blockIdx.x, t = threadIdx.x;
    float v = X[t*ncols + col] + bias[col];
    float s = v, ss = v*v;
    #pragma unroll
    for (int o = 16; o > 0; o >>= 1) {
        s  += __shfl_down_sync(0xffffffffu, s,  o);
        ss += __shfl_down_sync(0xffffffffu, ss, o);
    }
    __shared__ float ws[4], wss[4];
    __shared__ float sm, sscale;
    int wid = t >> 5, lane = t & 31;
    if (lane == 0) { ws[wid] = s; wss[wid] = ss; }
    __syncthreads();
    if (t == 0) {
        float S = ws[0]+ws[1]+ws[2]+ws[3];
        float SS = wss[0]+wss[1]+wss[2]+wss[3];
        float m = S*(1.f/BGRAPH);
        sm = m; sscale = rsqrtf(SS*(1.f/BGRAPH) - m*m + EPSV);
    }
    __syncthreads();
    float o = (v - sm)*sscale*gam[col] + bet[col];
    Y[t*ncols + col] = fmaxf(o, 0.f);
}
__global__ void k_head(const float* __restrict__ a3, const float* __restrict__ W4,
                       const float* __restrict__ b4, float* __restrict__ out)
{
    int b = blockIdx.x, lane = threadIdx.x;
    float s0 = 0.f, s1 = 0.f;
    for (int i = lane; i < H2; i += 32) {
        float v = a3[b*H2 + i];
        s0 = fmaf(v, W4[i*2+0], s0);
        s1 = fmaf(v, W4[i*2+1], s1);
    }
    #pragma unroll
    for (int o = 16; o > 0; o >>= 1) {
        s0 += __shfl_down_sync(0xffffffffu, s0, o);
        s1 += __shfl_down_sync(0xffffffffu, s1, o);
    }
    if (lane == 0) {
        float l0 = s0 + b4[0], l1 = s1 + b4[1];
        float m = fmaxf(l0, l1);
        float lse = m + logf(expf(l0-m) + expf(l1-m));
        out[b*2+0] = l0 - lse;
        out[b*2+1] = l1 - lse;
    }
}

// ---------------- launch ----------------
extern "C" void kernel_launch(void* const* d_in, const int* in_sizes, int n_in,
                              void* d_out, int out_size)
{
    const float* x    = (const float*)d_in[0];
    const int*   esrc = (const int*)d_in[1];
    const int*   edst = (const int*)d_in[2];
    const float* Wc1  = (const float*)d_in[4];
    const float* bc1  = (const float*)d_in[5];
    const float* Wc2  = (const float*)d_in[6];
    const float* bc2  = (const float*)d_in[7];
    const float* Wc3  = (const float*)d_in[8];
    const float* bc3  = (const float*)d_in[9];
    const float* bn_g = (const float*)d_in[10];
    const float* bn_b = (const float*)d_in[11];
    const float* bnh_g= (const float*)d_in[12];
    const float* bnh_b= (const float*)d_in[13];
    const float* W1   = (const float*)d_in[14];
    const float* b1   = (const float*)d_in[15];
    const float* g1   = (const float*)d_in[16];
    const float* be1  = (const float*)d_in[17];
    const float* W2   = (const float*)d_in[18];
    const float* b2   = (const float*)d_in[19];
    const float* g2   = (const float*)d_in[20];
    const float* be2  = (const float*)d_in[21];
    const float* W3   = (const float*)d_in[22];
    const float* b3   = (const float*)d_in[23];
    const float* g3   = (const float*)d_in[24];
    const float* be3  = (const float*)d_in[25];
    const float* W4   = (const float*)d_in[26];
    const float* b4   = (const float*)d_in[27];
    float* out = (float*)d_out;

    const int DSMH = 3*9216*2;   // 55296 B (fp16 GEMM, 64x128, BK=32, 3 stages)
    cudaFuncSetAttribute(gkh<0>, cudaFuncAttributeMaxDynamicSharedMemorySize, DSMH);
    cudaFuncSetAttribute(gkh<1>, cudaFuncAttributeMaxDynamicSharedMemorySize, DSMH);
    cudaFuncSetAttribute(gkh<2>, cudaFuncAttributeMaxDynamicSharedMemorySize, DSMH);

    void *pDinv, *pAh, *pXh, *pHh, *pX1, *pX2, *pX3, *pZh, *pW1h, *pHp, *pA1, *pA2, *pA3, *pWh;
    cudaGetSymbolAddress(&pDinv, g_dinv);
    cudaGetSymbolAddress(&pAh,  g_Ah);
    cudaGetSymbolAddress(&pXh,  g_xh);
    cudaGetSymbolAddress(&pHh,  g_hh);
    cudaGetSymbolAddress(&pX1,  g_x1h);
    cudaGetSymbolAddress(&pX2,  g_x2h);
    cudaGetSymbolAddress(&pX3,  g_x3h);
    cudaGetSymbolAddress(&pZh,  g_zh);
    cudaGetSymbolAddress(&pW1h, g_w1h);
    cudaGetSymbolAddress(&pHp,  g_hpool);
    cudaGetSymbolAddress(&pA1,  g_a1);
    cudaGetSymbolAddress(&pA2,  g_a2);
    cudaGetSymbolAddress(&pA3,  g_a3);
    cudaGetSymbolAddress(&pWh,  g_wh);

    const __half* wh = (const __half*)pWh;
    const __half* xh = (const __half*)pXh;
    const __half* Ah = (const __half*)pAh;
    const __half* hh = (const __half*)pHh;
    const __half* zh = (const __half*)pZh;
    const __half* w1h = (const __half*)pW1h;

    // launch order: first fp16 GEMM at index 6 (ncu capture slot)
    cudaMemsetAsync(pHh, 0, (size_t)BGRAPH*CCH*AP*2, 0);             // 0
    cudaMemsetAsync(pDinv, 0, (size_t)NNODE*4, 0);                   // 1
    cudaMemsetAsync(pAh, 0, (size_t)BGRAPH*AP*AP*2, 0);              // 2
    k_count_deg<<<(NEDGE+255)/256, 256>>>(edst);                     // 3
    k_prep<<<(3*CCH*(AP/16)+255)/256, 256>>>(Wc1, Wc2, Wc3);         // 4
    k_xh<<<(NNODE*(AP/16)+255)/256, 256>>>(x);                       // 5
    gkh<0><<<dim3(720,1), 256, DSMH>>>(xh, wh, nullptr, nullptr, nullptr,  // 6 <- ncu
                                       AP, AP, NNODE, AP);
    k_make_dinv<<<(NNODE+255)/256, 256>>>();                         // 7
    k_build<<<(NEDGE+NNODE+255)/256, 256>>>(esrc, edst);             // 8
    k_w1h<<<(H1*(ZP/16)+255)/256, 256>>>(W1);                        // 9

    gkh<1><<<dim3(6,BGRAPH), 256, DSMH>>>(Ah, hh, bc1, (__half*)pX1, nullptr, AP, AP, FN, AP);
    gkh<0><<<dim3(720,1), 256, DSMH>>>((const __half*)pX1, wh + (size_t)CCH*AP, nullptr, nullptr,
                                       nullptr, CCH, AP, NNODE, CCH);
    gkh<1><<<dim3(6,BGRAPH), 256, DSMH>>>(Ah, hh, bc2, (__half*)pX2, nullptr, AP, AP, FN, AP);
    gkh<0><<<dim3(720,1), 256, DSMH>>>((const __half*)pX2, wh + (size_t)2*CCH*AP, nullptr, nullptr,
                                       nullptr, CCH, AP, NNODE, CCH);
    gkh<1><<<dim3(6,BGRAPH), 256, DSMH>>>(Ah, hh, bc3, (__half*)pX3, nullptr, AP, AP, FN, AP);

    // features
    k_x0_bn<<<FN, 384>>>(x, bn_g, bn_b, (__half*)pZh);
    k_pool<<<dim3(BGRAPH,3), CCH>>>((const __half*)pX1, (const __half*)pX2,
                                    (const __half*)pX3, (float*)pHp);
    k_bn_pool<<<1, 1024>>>((const float*)pHp, bnh_g, bnh_b, (__half*)pZh);

    // MLP head: zW1 fp16 split-K, then tf32 small layers
    cudaMemsetAsync(pA1, 0, (size_t)BGRAPH*H1*4, 0);
    gkh<2><<<dim3(2,4,64), 256, DSMH>>>(zh, w1h, nullptr, nullptr, (float*)pA1,
                                        ZP, ZP, BGRAPH, 1024);
    k_bn_relu<<<H1, 128>>>((const float*)pA1, b1, g1, be1, (float*)pA1, H1);
    mmak<<<dim3(1,2), 256>>>((const float*)pA1, W2, (float*)pA2, BGRAPH, H2, H1);
    k_bn_relu<<<H2, 128>>>((const float*)pA2, b2, g2, be2, (float*)pA2, H2);
    mmak<<<dim3(1,2), 256>>>((const float*)pA2, W3, (float*)pA3, BGRAPH, H2, H2);
    k_bn_relu<<<H2, 128>>>((const float*)pA3, b3, g3, be3, (float*)pA3, H2);
    k_head<<<BGRAPH, 32>>>((const float*)pA3, W4, b4, out);
}

// round 14
// speedup vs baseline: 1.1163x; 1.0688x over previous
#include <cuda_runtime.h>
#include <cuda_fp16.h>
#include <math.h>
#include <stdint.h>

#define FN 360
#define BGRAPH 128
#define NNODE (FN*BGRAPH)
#define NEDGE 1000000
#define CCH 128
#define TRI 64980
#define D1 65364
#define ZP 65536
#define H1 512
#define H2 256
#define EPSV 1e-5f
#define PADK 136
#define AP 384

// ---------------- scratch ----------------
__device__ __align__(16) float  g_dinv[NNODE];
__device__ __align__(16) __half g_Ah[(size_t)BGRAPH*AP*AP];   // fp16 adjacency, ilv16 k
__device__ __align__(16) __half g_xh[(size_t)NNODE*AP];       // fp16 x, ilv16 k
__device__ __align__(16) __half g_wh[(size_t)3*CCH*AP];       // fp16 W^T, ilv16 k
__device__ __align__(16) __half g_hh[(size_t)BGRAPH*CCH*AP];  // fp16 h^T [b][c][j ilv16]
__device__ __align__(16) __half g_x1h[(size_t)NNODE*CCH];
__device__ __align__(16) __half g_x2h[(size_t)NNODE*CCH];
__device__ __align__(16) __half g_x3h[(size_t)NNODE*CCH];
__device__ __align__(16) __half g_zh[(size_t)BGRAPH*ZP];      // fp16 z, ilv16 cols
__device__ __align__(16) __half g_w1h[(size_t)H1*ZP];         // fp16 W1^T [n][k ilv16]
__device__ __align__(16) float  g_hpool[BGRAPH*384];
__device__ __align__(16) float  g_a1[BGRAPH*H1];
__device__ __align__(16) float  g_a2[BGRAPH*H2];
__device__ __align__(16) float  g_a3[BGRAPH*H2];

// ---------------- helpers ----------------
__device__ __forceinline__ uint32_t f2tf(float f) {
    uint32_t u; asm("cvt.rna.tf32.f32 %0, %1;" : "=r"(u) : "f"(f)); return u;
}
// fp16 ilv16: halfs at pos 4kt..4kt+3 hold k = {2kt,2kt+1,2kt+8,2kt+9}
__device__ __forceinline__ int pl16(int j)  { int p=j>>1, b=j&1; return ((p&3)<<2)|(((p>>2)&1)<<1)|b; }
__device__ __forceinline__ int ilv16(int c) { return (c & ~15) + pl16(c & 15); }
__device__ __forceinline__ int orig16p(int q){ int b=q&1, t=(q>>1)&7; int p=((t&1)<<2)|(t>>1); return 2*p+b; }
__device__ __forceinline__ float fast_tanh(float x) {
    float e = __expf(2.0f*x);
    return 1.0f - __fdividef(2.0f, e + 1.0f);
}
__device__ __forceinline__ uint32_t s2u(const void* p) {
    uint32_t a;
    asm("{ .reg .u64 t; cvta.to.shared.u64 t, %1; cvt.u32.u64 %0, t; }" : "=r"(a) : "l"(p));
    return a;
}
__device__ __forceinline__ void cpa16(uint32_t d, const void* g) {
    asm volatile("cp.async.cg.shared.global [%0], [%1], 16;" :: "r"(d), "l"(g));
}
__device__ __forceinline__ void mma8(float* c, const uint32_t* a, const uint32_t* b) {
    asm volatile("mma.sync.aligned.m16n8k8.row.col.f32.tf32.tf32.f32 "
        "{%0,%1,%2,%3}, {%4,%5,%6,%7}, {%8,%9}, {%0,%1,%2,%3};"
        : "+f"(c[0]), "+f"(c[1]), "+f"(c[2]), "+f"(c[3])
        : "r"(a[0]), "r"(a[1]), "r"(a[2]), "r"(a[3]), "r"(b[0]), "r"(b[1]));
}
__device__ __forceinline__ void mma16(float* c, const uint32_t* a, const uint32_t* b) {
    asm volatile("mma.sync.aligned.m16n8k16.row.col.f32.f16.f16.f32 "
        "{%0,%1,%2,%3}, {%4,%5,%6,%7}, {%8,%9}, {%0,%1,%2,%3};"
        : "+f"(c[0]), "+f"(c[1]), "+f"(c[2]), "+f"(c[3])
        : "r"(a[0]), "r"(a[1]), "r"(a[2]), "r"(a[3]), "r"(b[0]), "r"(b[1]));
}

// ---------------- prep ----------------
__global__ void k_prep(const float* __restrict__ Wc1, const float* __restrict__ Wc2,
                       const float* __restrict__ Wc3) {
    int i = blockIdx.x*blockDim.x + threadIdx.x;
    if (i >= 3*CCH*(AP/16)) return;
    int w = i / (CCH*(AP/16));
    int r = (i / (AP/16)) % CCH;
    int grp = i % (AP/16);
    const float* W = (w==0) ? Wc1 : (w==1) ? Wc2 : Wc3;
    int KW = (w==0) ? FN : CCH;
    __align__(16) __half o[16];
    #pragma unroll
    for (int j = 0; j < 16; j++) {
        int k = grp*16 + j;
        o[pl16(j)] = (k < KW) ? __float2half_rn(W[k*CCH + r]) : __half(0.f);
    }
    __half* dst = g_wh + ((size_t)(w*CCH + r))*AP + grp*16;
    ((uint4*)dst)[0] = ((uint4*)o)[0];
    ((uint4*)dst)[1] = ((uint4*)o)[1];
}
__global__ void k_xh(const float* __restrict__ x) {
    int i = blockIdx.x*blockDim.x + threadIdx.x;
    if (i >= NNODE*(AP/16)) return;
    int n = i / (AP/16), grp = i % (AP/16);
    __align__(16) __half o[16];
    #pragma unroll
    for (int j = 0; j < 16; j++) {
        int k = grp*16 + j;
        o[pl16(j)] = (k < FN) ? __float2half_rn(x[(size_t)n*FN + k]) : __half(0.f);
    }
    __half* dst = g_xh + (size_t)n*AP + grp*16;
    ((uint4*)dst)[0] = ((uint4*)o)[0];
    ((uint4*)dst)[1] = ((uint4*)o)[1];
}
__global__ void k_w1h(const float* __restrict__ W1) {
    int i = blockIdx.x*blockDim.x + threadIdx.x;
    if (i >= H1*(ZP/16)) return;
    int n = i & (H1-1);
    int grp = i >> 9;
    __align__(16) __half o[16];
    #pragma unroll
    for (int j = 0; j < 16; j++) {
        int k = grp*16 + j;
        o[pl16(j)] = (k < D1) ? __float2half_rn(W1[(size_t)k*H1 + n]) : __half(0.f);
    }
    __half* dst = g_w1h + (size_t)n*ZP + grp*16;
    ((uint4*)dst)[0] = ((uint4*)o)[0];
    ((uint4*)dst)[1] = ((uint4*)o)[1];
}
__global__ void k_count_deg(const int* __restrict__ dst) {
    int i = blockIdx.x*blockDim.x + threadIdx.x;
    if (i < NEDGE) atomicAdd(&g_dinv[dst[i]], 1.0f);
}
__global__ void k_make_dinv() {
    int i = blockIdx.x*blockDim.x + threadIdx.x;
    if (i < NNODE) g_dinv[i] = rsqrtf(g_dinv[i] + 1.0f);
}
__global__ void k_build(const int* __restrict__ src, const int* __restrict__ dst) {
    int i = blockIdx.x*blockDim.x + threadIdx.x;
    if (i < NEDGE) {
        int d = dst[i], s = src[i];
        int b = d / FN, r = d - b*FN, c = s - b*FN;
        atomicAdd(&g_Ah[((size_t)b*AP + r)*AP + ilv16(c)],
                  __float2half_rn(g_dinv[s]*g_dinv[d]));
    } else if (i < NEDGE + NNODE) {
        int n = i - NEDGE, b = n / FN, r = n - b*FN;
        atomicAdd(&g_Ah[((size_t)b*AP + r)*AP + ilv16(r)],
                  __float2half_rn(g_dinv[n]*g_dinv[n]));
    }
}

// ---------------- fp16 HMMA GEMM, 64x128 tile, BK=32, 3-stage cp.async -------
// MODE 0: XW -> g_hh. grid(720). MODE 1: AH -> xs = tanh. grid(6, BGRAPH).
// MODE 2: zW1 split-K, kbeg = koff + z*1024, fp32 atomicAdd.
template<int MODE>
__global__ __launch_bounds__(256, 3)
void gkh(const __half* __restrict__ Ag, const __half* __restrict__ Bg,
         const float* __restrict__ bias, __half* __restrict__ Cg,
         float* __restrict__ Cf, int lda, int ldb, int M, int K, int koff)
{
    extern __shared__ __align__(16) __half dynh[];
    const int STG = 9216;
    const int tid = threadIdx.x, lane = tid & 31, w = tid >> 5;
    const int wm = (w & 1)*32, wn = (w >> 1)*32;
    const int g = lane >> 2, kt = lane & 3;
    const int rowBase = blockIdx.x*64;
    const int bOff = (MODE == 2) ? blockIdx.y*128 : 0;

    if (MODE == 1) {
        Ag += (size_t)blockIdx.y * AP * AP;
        Bg += (size_t)blockIdx.y * CCH * AP;
    }
    const int kbeg = (MODE == 2) ? (koff + blockIdx.z*1024) : 0;
    const int am = tid >> 2;
    const int ak = (tid & 3) * 8;
    const int bm = tid >> 1;
    const int bk = (tid & 1) * 16;

    auto load_chunk = [&](int c, int stg) {
        int k0 = kbeg + c*32;
        __half* As = dynh + stg*STG;
        __half* Bs = As + 3072;
        const __half* ar = Ag + (size_t)(rowBase + am)*lda + k0 + ak;
        cpa16(s2u(As + am*48 + ak), ar);
        const __half* br = Bg + (size_t)(bOff + bm)*ldb + k0 + bk;
        uint32_t bd = s2u(Bs + bm*48 + bk);
        cpa16(bd,      br);
        cpa16(bd + 16, br + 8);
        asm volatile("cp.async.commit_group;" ::: "memory");
    };

    float acc[2][4][4];
    #pragma unroll
    for (int mi = 0; mi < 2; mi++)
        #pragma unroll
        for (int nj = 0; nj < 4; nj++)
            #pragma unroll
            for (int r = 0; r < 4; r++) acc[mi][nj][r] = 0.f;

    const int nch = K >> 5;
    load_chunk(0, 0);
    load_chunk(1, 1);
    for (int c = 0; c < nch; c++) {
        int buf = c % 3;
        if (c + 2 < nch) {
            load_chunk(c + 2, (c + 2) % 3);
            asm volatile("cp.async.wait_group 2;" ::: "memory");
        } else if (c + 1 < nch) {
            asm volatile("cp.async.wait_group 1;" ::: "memory");
        } else {
            asm volatile("cp.async.wait_group 0;" ::: "memory");
        }
        __syncthreads();
        const __half* As = dynh + buf*STG;
        const __half* Bs = As + 3072;
        #pragma unroll
        for (int ks = 0; ks < 2; ks++) {
            uint32_t af[2][4], bf[4][2];
            #pragma unroll
            for (int mi = 0; mi < 2; mi++) {
                int m = wm + mi*16 + g;
                uint2 va = *(const uint2*)&As[m*48     + ks*16 + 4*kt];
                uint2 vb = *(const uint2*)&As[(m+8)*48 + ks*16 + 4*kt];
                af[mi][0] = va.x;
                af[mi][1] = vb.x;
                af[mi][2] = va.y;
                af[mi][3] = vb.y;
            }
            #pragma unroll
            for (int nj = 0; nj < 4; nj++) {
                int n = wn + nj*8 + g;
                uint2 u = *(const uint2*)&Bs[n*48 + ks*16 + 4*kt];
                bf[nj][0] = u.x;
                bf[nj][1] = u.y;
            }
            #pragma unroll
            for (int mi = 0; mi < 2; mi++)
                #pragma unroll
                for (int nj = 0; nj < 4; nj++)
                    mma16(acc[mi][nj], af[mi], bf[nj]);
        }
        __syncthreads();
    }

    #pragma unroll
    for (int mi = 0; mi < 2; mi++)
        #pragma unroll
        for (int nj = 0; nj < 4; nj++)
            #pragma unroll
            for (int r = 0; r < 4; r++) {
                int gm = rowBase + wm + mi*16 + g + (r>>1)*8;
                int gn = wn + nj*8 + kt*2 + (r&1);
                float v = acc[mi][nj][r];
                if (MODE == 0) {
                    int b = gm / FN, j = gm - b*FN;
                    g_hh[((size_t)b*CCH + gn)*AP + ilv16(j)] = __float2half_rn(v);
                } else if (MODE == 1) {
                    if (gm < M) {
                        __half* dst = Cg + ((size_t)blockIdx.y*FN + gm)*CCH;
                        dst[ilv16(gn)] = __float2half_rn(fast_tanh(v + __ldg(bias + gn)));
                    }
                } else {
                    atomicAdd(&Cf[(size_t)gm*H1 + bOff + gn], v);
                }
            }
}

// ---------------- legacy tf32 mma.sync GEMM (small MLP layers) ----------------
__global__ __launch_bounds__(256)
void mmak(const float* __restrict__ A, const float* __restrict__ Bm,
          float* __restrict__ C, int M, int N, int K)
{
    __shared__ uint32_t As[2][16][PADK];
    __shared__ uint32_t Bs[2][16][PADK];
    const int tid = threadIdx.x, lane = tid & 31, w = tid >> 5;
    const int wm = (w & 1)*64, wn = (w >> 1)*32;
    const int g = lane >> 2, kt = lane & 3;
    const int rowBase = blockIdx.x*128, colBase = blockIdx.y*128;
    const int aRow = tid >> 1, aCol = (tid & 1)*8;
    const int bRow = tid >> 4, bCol = (tid & 15)*8;
    float acc[4][4][4];
    #pragma unroll
    for (int mi = 0; mi < 4; mi++)
        #pragma unroll
        for (int nj = 0; nj < 4; nj++)
            #pragma unroll
            for (int r = 0; r < 4; r++) acc[mi][nj][r] = 0.f;
    const int gmA = rowBase + aRow;
    float4 pa[2], pb[2];
    auto loadT = [&](int k0) {
        #pragma unroll
        for (int h = 0; h < 2; h++) {
            int gk = k0 + aCol + h*4;
            float4 v = make_float4(0.f,0.f,0.f,0.f);
            if (gmA < M && gk + 3 < K) v = *(const float4*)(A + (size_t)gmA*K + gk);
            pa[h] = v;
        }
        int gk = k0 + bRow;
        #pragma unroll
        for (int h = 0; h < 2; h++) {
            int gn = colBase + bCol + h*4;
            float4 v = make_float4(0.f,0.f,0.f,0.f);
            if (gk < K && gn < N) v = *(const float4*)(Bm + (size_t)gk*N + gn);
            pb[h] = v;
        }
    };
    auto storeT = [&](int buf) {
        #pragma unroll
        for (int h = 0; h < 2; h++) {
            As[buf][aCol+h*4+0][aRow] = f2tf(pa[h].x);
            As[buf][aCol+h*4+1][aRow] = f2tf(pa[h].y);
            As[buf][aCol+h*4+2][aRow] = f2tf(pa[h].z);
            As[buf][aCol+h*4+3][aRow] = f2tf(pa[h].w);
            Bs[buf][bRow][bCol+h*4+0] = f2tf(pb[h].x);
            Bs[buf][bRow][bCol+h*4+1] = f2tf(pb[h].y);
            Bs[buf][bRow][bCol+h*4+2] = f2tf(pb[h].z);
            Bs[buf][bRow][bCol+h*4+3] = f2tf(pb[h].w);
        }
    };
    auto comp = [&](int buf) {
        #pragma unroll
        for (int ks = 0; ks < 2; ks++) {
            uint32_t af[4][4], bf[4][2];
            #pragma unroll
            for (int mi = 0; mi < 4; mi++) {
                int m = wm + mi*16;
                af[mi][0] = As[buf][ks*8+kt  ][m+g  ];
                af[mi][1] = As[buf][ks*8+kt  ][m+g+8];
                af[mi][2] = As[buf][ks*8+kt+4][m+g  ];
                af[mi][3] = As[buf][ks*8+kt+4][m+g+8];
            }
            #pragma unroll
            for (int nj = 0; nj < 4; nj++) {
                int n = wn + nj*8;
                bf[nj][0] = Bs[buf][ks*8+kt  ][n+g];
                bf[nj][1] = Bs[buf][ks*8+kt+4][n+g];
            }
            #pragma unroll
            for (int mi = 0; mi < 4; mi++)
                #pragma unroll
                for (int nj = 0; nj < 4; nj++) mma8(acc[mi][nj], af[mi], bf[nj]);
        }
    };
    const int nIter = (K + 15) >> 4;
    loadT(0); storeT(0); __syncthreads();
    for (int t = 1; t < nIter; t++) {
        loadT(t*16);
        comp((t-1) & 1);
        storeT(t & 1);
        __syncthreads();
    }
    comp((nIter-1) & 1);
    #pragma unroll
    for (int mi = 0; mi < 4; mi++)
        #pragma unroll
        for (int nj = 0; nj < 4; nj++)
            #pragma unroll
            for (int r = 0; r < 4; r++) {
                int gm = rowBase + wm + mi*16 + g + (r>>1)*8;
                int gn = colBase + wn + nj*8 + kt*2 + (r&1);
                if (gm < M && gn < N) C[(size_t)gm*N + gn] = acc[mi][nj][r];
            }
}

// ---------------- BN / pool / head ----------------
__global__ void k_x0_bn(const float* __restrict__ x, const float* __restrict__ g,
                        const float* __restrict__ be, __half* __restrict__ z)
{
    int r = blockIdx.x;
    int c = r + threadIdx.x;
    if (c >= FN) return;
    long j = (long)r*FN - (long)r*(r-1)/2 + (c - r);
    long zi = (j & ~15L) + pl16((int)(j & 15));
    float s = 0.f, ss = 0.f;
    for (int b = 0; b < BGRAPH; b++) {
        float v = x[((size_t)(b*FN + r))*FN + c];
        s += v; ss += v*v;
    }
    float m = s*(1.f/BGRAPH);
    float var = ss*(1.f/BGRAPH) - m*m;
    float sc = rsqrtf(var + EPSV)*g[j];
    float bb = be[j];
    for (int b = 0; b < BGRAPH; b++) {
        float v = x[((size_t)(b*FN + r))*FN + c];
        z[(size_t)b*ZP + zi] = __float2half_rn((v - m)*sc + bb);
    }
}
__global__ void k_pool(const __half* __restrict__ x1, const __half* __restrict__ x2,
                       const __half* __restrict__ x3, float* __restrict__ hp)
{
    int b = blockIdx.x, l = blockIdx.y, k = threadIdx.x;
    const __half* base = (l==0 ? x1 : l==1 ? x2 : x3) + (size_t)b*FN*CCH + k;
    float s0=0.f, s1=0.f, s2=0.f, s3=0.f;
    #pragma unroll 1
    for (int n = 0; n < FN; n += 4) {
        s0 += __half2float(base[(size_t)(n+0)*CCH]);
        s1 += __half2float(base[(size_t)(n+1)*CCH]);
        s2 += __half2float(base[(size_t)(n+2)*CCH]);
        s3 += __half2float(base[(size_t)(n+3)*CCH]);
    }
    int oc = (k & ~15) + orig16p(k & 15);
    hp[b*384 + l*CCH + oc] = (s0+s1+s2+s3)*(1.0f/FN);
}
__global__ void k_bn_pool(const float* __restrict__ hp, const float* __restrict__ g,
                          const float* __restrict__ be, __half* __restrict__ z)
{
    int j = blockIdx.x*blockDim.x + threadIdx.x;
    if (j >= ZP - TRI) return;
    long cg2 = (long)TRI + j;
    long zi = (cg2 & ~15L) + pl16((int)(cg2 & 15));
    if (j >= 384) {
        for (int b = 0; b < BGRAPH; b++) z[(size_t)b*ZP + zi] = __half(0.f);
        return;
    }
    float s = 0.f, ss = 0.f;
    for (int b = 0; b < BGRAPH; b++) { float v = hp[b*384 + j]; s += v; ss += v*v; }
    float m = s*(1.f/BGRAPH);
    float var = ss*(1.f/BGRAPH) - m*m;
    float sc = rsqrtf(var + EPSV)*g[j];
    float bb = be[j];
    for (int b = 0; b < BGRAPH; b++)
        z[(size_t)b*ZP + zi] = __float2half_rn((hp[b*384 + j] - m)*sc + bb);
}
__global__ void k_bn_relu(const float* __restrict__ X, const float* __restrict__ bias,
                          const float* __restrict__ gam, const float* __restrict__ bet,
                          float* __restrict__ Y, int ncols)
{
    int col = blockIdx.x, t = threadIdx.x;
    float v = X[t*ncols + col] + bias[col];
    float s = v, ss = v*v;
    #pragma unroll
    for (int o = 16; o > 0; o >>= 1) {
        s  += __shfl_down_sync(0xffffffffu, s,  o);
        ss += __shfl_down_sync(0xffffffffu, ss, o);
    }
    __shared__ float ws[4], wss[4];
    __shared__ float sm, sscale;
    int wid = t >> 5, lane = t & 31;
    if (lane == 0) { ws[wid] = s; wss[wid] = ss; }
    __syncthreads();
    if (t == 0) {
        float S = ws[0]+ws[1]+ws[2]+ws[3];
        float SS = wss[0]+wss[1]+wss[2]+wss[3];
        float m = S*(1.f/BGRAPH);
        sm = m; sscale = rsqrtf(SS*(1.f/BGRAPH) - m*m + EPSV);
    }
    __syncthreads();
    float o = (v - sm)*sscale*gam[col] + bet[col];
    Y[t*ncols + col] = fmaxf(o, 0.f);
}
__global__ void k_head(const float* __restrict__ a3, const float* __restrict__ W4,
                       const float* __restrict__ b4, float* __restrict__ out)
{
    int b = blockIdx.x, lane = threadIdx.x;
    float s0 = 0.f, s1 = 0.f;
    for (int i = lane; i < H2; i += 32) {
        float v = a3[b*H2 + i];
        s0 = fmaf(v, W4[i*2+0], s0);
        s1 = fmaf(v, W4[i*2+1], s1);
    }
    #pragma unroll
    for (int o = 16; o > 0; o >>= 1) {
        s0 += __shfl_down_sync(0xffffffffu, s0, o);
        s1 += __shfl_down_sync(0xffffffffu, s1, o);
    }
    if (lane == 0) {
        float l0 = s0 + b4[0], l1 = s1 + b4[1];
        float m = fmaxf(l0, l1);
        float lse = m + logf(expf(l0-m) + expf(l1-m));
        out[b*2+0] = l0 - lse;
        out[b*2+1] = l1 - lse;
    }
}

// ---------------- launch ----------------
extern "C" void kernel_launch(void* const* d_in, const int* in_sizes, int n_in,
                              void* d_out, int out_size)
{
    const float* x    = (const float*)d_in[0];
    const int*   esrc = (const int*)d_in[1];
    const int*   edst = (const int*)d_in[2];
    const float* Wc1  = (const float*)d_in[4];
    const float* bc1  = (const float*)d_in[5];
    const float* Wc2  = (const float*)d_in[6];
    const float* bc2  = (const float*)d_in[7];
    const float* Wc3  = (const float*)d_in[8];
    const float* bc3  = (const float*)d_in[9];
    const float* bn_g = (const float*)d_in[10];
    const float* bn_b = (const float*)d_in[11];
    const float* bnh_g= (const float*)d_in[12];
    const float* bnh_b= (const float*)d_in[13];
    const float* W1   = (const float*)d_in[14];
    const float* b1   = (const float*)d_in[15];
    const float* g1   = (const float*)d_in[16];
    const float* be1  = (const float*)d_in[17];
    const float* W2   = (const float*)d_in[18];
    const float* b2   = (const float*)d_in[19];
    const float* g2   = (const float*)d_in[20];
    const float* be2  = (const float*)d_in[21];
    const float* W3   = (const float*)d_in[22];
    const float* b3   = (const float*)d_in[23];
    const float* g3   = (const float*)d_in[24];
    const float* be3  = (const float*)d_in[25];
    const float* W4   = (const float*)d_in[26];
    const float* b4   = (const float*)d_in[27];
    float* out = (float*)d_out;

    const int DSMH = 3*9216*2;
    cudaFuncSetAttribute(gkh<0>, cudaFuncAttributeMaxDynamicSharedMemorySize, DSMH);
    cudaFuncSetAttribute(gkh<1>, cudaFuncAttributeMaxDynamicSharedMemorySize, DSMH);
    cudaFuncSetAttribute(gkh<2>, cudaFuncAttributeMaxDynamicSharedMemorySize, DSMH);

    void *pDinv, *pAh, *pXh, *pHh, *pX1, *pX2, *pX3, *pZh, *pW1h, *pHp, *pA1, *pA2, *pA3, *pWh;
    cudaGetSymbolAddress(&pDinv, g_dinv);
    cudaGetSymbolAddress(&pAh,  g_Ah);
    cudaGetSymbolAddress(&pXh,  g_xh);
    cudaGetSymbolAddress(&pHh,  g_hh);
    cudaGetSymbolAddress(&pX1,  g_x1h);
    cudaGetSymbolAddress(&pX2,  g_x2h);
    cudaGetSymbolAddress(&pX3,  g_x3h);
    cudaGetSymbolAddress(&pZh,  g_zh);
    cudaGetSymbolAddress(&pW1h, g_w1h);
    cudaGetSymbolAddress(&pHp,  g_hpool);
    cudaGetSymbolAddress(&pA1,  g_a1);
    cudaGetSymbolAddress(&pA2,  g_a2);
    cudaGetSymbolAddress(&pA3,  g_a3);
    cudaGetSymbolAddress(&pWh,  g_wh);

    const __half* wh = (const __half*)pWh;
    const __half* xh = (const __half*)pXh;
    const __half* Ah = (const __half*)pAh;
    const __half* hh = (const __half*)pHh;
    const __half* zh = (const __half*)pZh;
    const __half* w1h = (const __half*)pW1h;

    // ---- fork two side streams off the capture stream (stream 0) ----
    cudaStream_t s1, s2;
    cudaStreamCreateWithFlags(&s1, cudaStreamNonBlocking);
    cudaStreamCreateWithFlags(&s2, cudaStreamNonBlocking);
    cudaEvent_t eFork, eAdj, eZ;
    cudaEventCreateWithFlags(&eFork, cudaEventDisableTiming);
    cudaEventCreateWithFlags(&eAdj,  cudaEventDisableTiming);
    cudaEventCreateWithFlags(&eZ,    cudaEventDisableTiming);

    cudaEventRecord(eFork, 0);
    cudaStreamWaitEvent(s1, eFork, 0);
    cudaStreamWaitEvent(s2, eFork, 0);

    // s1: adjacency chain
    cudaMemsetAsync(pDinv, 0, (size_t)NNODE*4, s1);
    cudaMemsetAsync(pAh, 0, (size_t)BGRAPH*AP*AP*2, s1);
    k_count_deg<<<(NEDGE+255)/256, 256, 0, s1>>>(edst);
    k_make_dinv<<<(NNODE+255)/256, 256, 0, s1>>>();
    k_build<<<(NEDGE+NNODE+255)/256, 256, 0, s1>>>(esrc, edst);
    cudaEventRecord(eAdj, s1);

    // s2: W1 conversion + triu BN + early zW1 k-splits (cols < 64512, all from x0_bn)
    k_w1h<<<(H1*(ZP/16)+255)/256, 256, 0, s2>>>(W1);
    k_x0_bn<<<FN, 384, 0, s2>>>(x, bn_g, bn_b, (__half*)pZh);
    cudaMemsetAsync(pA1, 0, (size_t)BGRAPH*H1*4, s2);
    gkh<2><<<dim3(2,4,63), 256, DSMH, s2>>>(zh, w1h, nullptr, nullptr, (float*)pA1,
                                            ZP, ZP, BGRAPH, 1024, 0);
    cudaEventRecord(eZ, s2);

    // s0 (capture stream): XW/AH chain
    cudaMemsetAsync(pHh, 0, (size_t)BGRAPH*CCH*AP*2, 0);
    k_prep<<<(3*CCH*(AP/16)+255)/256, 256>>>(Wc1, Wc2, Wc3);
    k_xh<<<(NNODE*(AP/16)+255)/256, 256>>>(x);
    gkh<0><<<dim3(720,1), 256, DSMH>>>(xh, wh, nullptr, nullptr, nullptr,
                                       AP, AP, NNODE, AP, 0);
    cudaStreamWaitEvent(0, eAdj, 0);
    gkh<1><<<dim3(6,BGRAPH), 256, DSMH>>>(Ah, hh, bc1, (__half*)pX1, nullptr, AP, AP, FN, AP, 0);
    gkh<0><<<dim3(720,1), 256, DSMH>>>((const __half*)pX1, wh + (size_t)CCH*AP, nullptr, nullptr,
                                       nullptr, CCH, AP, NNODE, CCH, 0);
    gkh<1><<<dim3(6,BGRAPH), 256, DSMH>>>(Ah, hh, bc2, (__half*)pX2, nullptr, AP, AP, FN, AP, 0);
    gkh<0><<<dim3(720,1), 256, DSMH>>>((const __half*)pX2, wh + (size_t)2*CCH*AP, nullptr, nullptr,
                                       nullptr, CCH, AP, NNODE, CCH, 0);
    gkh<1><<<dim3(6,BGRAPH), 256, DSMH>>>(Ah, hh, bc3, (__half*)pX3, nullptr, AP, AP, FN, AP, 0);

    k_pool<<<dim3(BGRAPH,3), CCH>>>((const __half*)pX1, (const __half*)pX2,
                                    (const __half*)pX3, (float*)pHp);
    k_bn_pool<<<1, 1024>>>((const float*)pHp, bnh_g, bnh_b, (__half*)pZh);

    // join s2, then last zW1 split (cols 64512..65535: pooled + pads)
    cudaStreamWaitEvent(0, eZ, 0);
    gkh<2><<<dim3(2,4,1), 256, DSMH>>>(zh, w1h, nullptr, nullptr, (float*)pA1,
                                       ZP, ZP, BGRAPH, 1024, 64512);
    k_bn_relu<<<H1, 128>>>((const float*)pA1, b1, g1, be1, (float*)pA1, H1);
    mmak<<<dim3(1,2), 256>>>((const float*)pA1, W2, (float*)pA2, BGRAPH, H2, H1);
    k_bn_relu<<<H2, 128>>>((const float*)pA2, b2, g2, be2, (float*)pA2, H2);
    mmak<<<dim3(1,2), 256>>>((const float*)pA2, W3, (float*)pA3, BGRAPH, H2, H2);
    k_bn_relu<<<H2, 128>>>((const float*)pA3, b3, g3, be3, (float*)pA3, H2);
    k_head<<<BGRAPH, 32>>>((const float*)pA3, W4, b4, out);

    // cleanup (deferred destruction; no syncs)
    cudaEventDestroy(eFork);
    cudaEventDestroy(eAdj);
    cudaEventDestroy(eZ);
    cudaStreamDestroy(s1);
    cudaStreamDestroy(s2);
}

// round 15
// speedup vs baseline: 1.1663x; 1.0448x over previous
#include <cuda_runtime.h>
#include <cuda_fp16.h>
#include <math.h>
#include <stdint.h>

#define FN 360
#define BGRAPH 128
#define NNODE (FN*BGRAPH)
#define NEDGE 1000000
#define CCH 128
#define TRI 64980
#define D1 65364
#define ZP 65536
#define H1 512
#define H2 256
#define EPSV 1e-5f
#define PADK 136
#define AP 384

// ---------------- scratch ----------------
__device__ __align__(16) float  g_dinv[NNODE];
__device__ __align__(16) __half g_Ah[(size_t)BGRAPH*AP*AP];   // fp16 adjacency, ilv16 k
__device__ __align__(16) __half g_xh[(size_t)NNODE*AP];       // fp16 x, ilv16 k
__device__ __align__(16) __half g_wh[(size_t)3*CCH*AP];       // fp16 W^T, ilv16 k
__device__ __align__(16) __half g_hh[(size_t)BGRAPH*CCH*AP];  // fp16 h^T [b][c][j ilv16]
__device__ __align__(16) __half g_x1h[(size_t)NNODE*CCH];
__device__ __align__(16) __half g_x2h[(size_t)NNODE*CCH];
__device__ __align__(16) __half g_x3h[(size_t)NNODE*CCH];
__device__ __align__(16) __half g_zh[(size_t)BGRAPH*ZP];      // fp16 z, ilv16 cols
__device__ __align__(16) __half g_w1h[(size_t)H1*ZP];         // fp16 W1^T [n][k ilv16]
__device__ __align__(16) float  g_hpool[BGRAPH*384];
__device__ __align__(16) float  g_a1[BGRAPH*H1];
__device__ __align__(16) float  g_a2[BGRAPH*H2];
__device__ __align__(16) float  g_a3[BGRAPH*H2];

// ---------------- helpers ----------------
__device__ __forceinline__ uint32_t f2tf(float f) {
    uint32_t u; asm("cvt.rna.tf32.f32 %0, %1;" : "=r"(u) : "f"(f)); return u;
}
// fp16 ilv16: halfs at pos 4kt..4kt+3 hold k = {2kt,2kt+1,2kt+8,2kt+9}
__device__ __forceinline__ int pl16(int j)  { int p=j>>1, b=j&1; return ((p&3)<<2)|(((p>>2)&1)<<1)|b; }
__device__ __forceinline__ int ilv16(int c) { return (c & ~15) + pl16(c & 15); }
__device__ __forceinline__ int orig16p(int q){ int b=q&1, t=(q>>1)&7; int p=((t&1)<<2)|(t>>1); return 2*p+b; }
__device__ __forceinline__ float fast_tanh(float x) {
    float e = __expf(2.0f*x);
    return 1.0f - __fdividef(2.0f, e + 1.0f);
}
__device__ __forceinline__ uint32_t s2u(const void* p) {
    uint32_t a;
    asm("{ .reg .u64 t; cvta.to.shared.u64 t, %1; cvt.u32.u64 %0, t; }" : "=r"(a) : "l"(p));
    return a;
}
__device__ __forceinline__ void cpa16(uint32_t d, const void* g) {
    asm volatile("cp.async.cg.shared.global [%0], [%1], 16;" :: "r"(d), "l"(g));
}
__device__ __forceinline__ void mma8(float* c, const uint32_t* a, const uint32_t* b) {
    asm volatile("mma.sync.aligned.m16n8k8.row.col.f32.tf32.tf32.f32 "
        "{%0,%1,%2,%3}, {%4,%5,%6,%7}, {%8,%9}, {%0,%1,%2,%3};"
        : "+f"(c[0]), "+f"(c[1]), "+f"(c[2]), "+f"(c[3])
        : "r"(a[0]), "r"(a[1]), "r"(a[2]), "r"(a[3]), "r"(b[0]), "r"(b[1]));
}
__device__ __forceinline__ void mma16(float* c, const uint32_t* a, const uint32_t* b) {
    asm volatile("mma.sync.aligned.m16n8k16.row.col.f32.f16.f16.f32 "
        "{%0,%1,%2,%3}, {%4,%5,%6,%7}, {%8,%9}, {%0,%1,%2,%3};"
        : "+f"(c[0]), "+f"(c[1]), "+f"(c[2]), "+f"(c[3])
        : "r"(a[0]), "r"(a[1]), "r"(a[2]), "r"(a[3]), "r"(b[0]), "r"(b[1]));
}

// ---------------- prep ----------------
__global__ void k_prep(const float* __restrict__ Wc1, const float* __restrict__ Wc2,
                       const float* __restrict__ Wc3) {
    int i = blockIdx.x*blockDim.x + threadIdx.x;
    if (i >= 3*CCH*(AP/16)) return;
    int w = i / (CCH*(AP/16));
    int r = (i / (AP/16)) % CCH;
    int grp = i % (AP/16);
    const float* W = (w==0) ? Wc1 : (w==1) ? Wc2 : Wc3;
    int KW = (w==0) ? FN : CCH;
    __align__(16) __half o[16];
    #pragma unroll
    for (int j = 0; j < 16; j++) {
        int k = grp*16 + j;
        o[pl16(j)] = (k < KW) ? __float2half_rn(W[k*CCH + r]) : __half(0.f);
    }
    __half* dst = g_wh + ((size_t)(w*CCH + r))*AP + grp*16;
    ((uint4*)dst)[0] = ((uint4*)o)[0];
    ((uint4*)dst)[1] = ((uint4*)o)[1];
}
__global__ void k_xh(const float* __restrict__ x) {
    int i = blockIdx.x*blockDim.x + threadIdx.x;
    if (i >= NNODE*(AP/16)) return;
    int n = i / (AP/16), grp = i % (AP/16);
    __align__(16) __half o[16];
    #pragma unroll
    for (int j = 0; j < 16; j++) {
        int k = grp*16 + j;
        o[pl16(j)] = (k < FN) ? __float2half_rn(x[(size_t)n*FN + k]) : __half(0.f);
    }
    __half* dst = g_xh + (size_t)n*AP + grp*16;
    ((uint4*)dst)[0] = ((uint4*)o)[0];
    ((uint4*)dst)[1] = ((uint4*)o)[1];
}
// coalesced W1 transpose-convert: 64k x 32n tiles via smem
__global__ void k_w1h(const float* __restrict__ W1) {
    __shared__ float s[64][33];
    int k0 = blockIdx.x * 64;
    int n0 = blockIdx.y * 32;
    int t = threadIdx.x;
    int nl = t & 31, kb = t >> 5;           // kb 0..7
    #pragma unroll
    for (int i = 0; i < 8; i++) {
        int k = k0 + kb*8 + i;
        s[kb*8 + i][nl] = (k < D1) ? W1[(size_t)k*H1 + n0 + nl] : 0.f;
    }
    __syncthreads();
    if (t < 128) {
        int nl2 = t >> 2, gl = t & 3;       // n within tile, k-group 0..3
        __align__(16) __half o[16];
        #pragma unroll
        for (int j = 0; j < 16; j++)
            o[pl16(j)] = __float2half_rn(s[gl*16 + j][nl2]);
        __half* dst = g_w1h + (size_t)(n0 + nl2)*ZP + k0 + gl*16;
        ((uint4*)dst)[0] = ((uint4*)o)[0];
        ((uint4*)dst)[1] = ((uint4*)o)[1];
    }
}
__global__ void k_count_deg(const int* __restrict__ dst) {
    int i = blockIdx.x*blockDim.x + threadIdx.x;
    if (i < NEDGE) atomicAdd(&g_dinv[dst[i]], 1.0f);
}
__global__ void k_make_dinv() {
    int i = blockIdx.x*blockDim.x + threadIdx.x;
    if (i < NNODE) g_dinv[i] = rsqrtf(g_dinv[i] + 1.0f);
}
__global__ void k_build(const int* __restrict__ src, const int* __restrict__ dst) {
    int i = blockIdx.x*blockDim.x + threadIdx.x;
    if (i < NEDGE) {
        int d = dst[i], s = src[i];
        int b = d / FN, r = d - b*FN, c = s - b*FN;
        atomicAdd(&g_Ah[((size_t)b*AP + r)*AP + ilv16(c)],
                  __float2half_rn(g_dinv[s]*g_dinv[d]));
    } else if (i < NEDGE + NNODE) {
        int n = i - NEDGE, b = n / FN, r = n - b*FN;
        atomicAdd(&g_Ah[((size_t)b*AP + r)*AP + ilv16(r)],
                  __float2half_rn(g_dinv[n]*g_dinv[n]));
    }
}

// ---------------- fp16 HMMA GEMM, 64x128 tile, BK=32, 3-stage cp.async -------
// MODE 0: XW -> g_hh. grid(720).
// MODE 1: AH -> xs = tanh(D+bias). grid(6, BGRAPH). FUSE=1: also h_next = xs@Wnext -> g_hh.
// MODE 2: zW1 split-K, kbeg = koff + z*1024, fp32 atomicAdd.
template<int MODE, int FUSE>
__global__ __launch_bounds__(256, 3)
void gkh(const __half* __restrict__ Ag, const __half* __restrict__ Bg,
         const float* __restrict__ bias, __half* __restrict__ Cg,
         float* __restrict__ Cf, const __half* __restrict__ Wnext,
         int lda, int ldb, int M, int K, int koff)
{
    extern __shared__ __align__(16) __half dynh[];
    const int STG = 9216;
    const int tid = threadIdx.x, lane = tid & 31, w = tid >> 5;
    const int wm = (w & 1)*32, wn = (w >> 1)*32;
    const int g = lane >> 2, kt = lane & 3;
    const int rowBase = blockIdx.x*64;
    const int bOff = (MODE == 2) ? blockIdx.y*128 : 0;

    if (MODE == 1) {
        Ag += (size_t)blockIdx.y * AP * AP;
        Bg += (size_t)blockIdx.y * CCH * AP;
    }
    const int kbeg = (MODE == 2) ? (koff + blockIdx.z*1024) : 0;
    const int am = tid >> 2;
    const int ak = (tid & 3) * 8;
    const int bm = tid >> 1;
    const int bk = (tid & 1) * 16;

    auto load_chunk = [&](int c, int stg) {
        int k0 = kbeg + c*32;
        __half* As = dynh + stg*STG;
        __half* Bs = As + 3072;
        const __half* ar = Ag + (size_t)(rowBase + am)*lda + k0 + ak;
        cpa16(s2u(As + am*48 + ak), ar);
        const __half* br = Bg + (size_t)(bOff + bm)*ldb + k0 + bk;
        uint32_t bd = s2u(Bs + bm*48 + bk);
        cpa16(bd,      br);
        cpa16(bd + 16, br + 8);
        asm volatile("cp.async.commit_group;" ::: "memory");
    };

    float acc[2][4][4];
    #pragma unroll
    for (int mi = 0; mi < 2; mi++)
        #pragma unroll
        for (int nj = 0; nj < 4; nj++)
            #pragma unroll
            for (int r = 0; r < 4; r++) acc[mi][nj][r] = 0.f;

    const int nch = K >> 5;
    load_chunk(0, 0);
    load_chunk(1, 1);
    for (int c = 0; c < nch; c++) {
        int buf = c % 3;
        if (c + 2 < nch) {
            load_chunk(c + 2, (c + 2) % 3);
            asm volatile("cp.async.wait_group 2;" ::: "memory");
        } else if (c + 1 < nch) {
            asm volatile("cp.async.wait_group 1;" ::: "memory");
        } else {
            asm volatile("cp.async.wait_group 0;" ::: "memory");
        }
        __syncthreads();
        const __half* As = dynh + buf*STG;
        const __half* Bs = As + 3072;
        #pragma unroll
        for (int ks = 0; ks < 2; ks++) {
            uint32_t af[2][4], bf[4][2];
            #pragma unroll
            for (int mi = 0; mi < 2; mi++) {
                int m = wm + mi*16 + g;
                uint2 va = *(const uint2*)&As[m*48     + ks*16 + 4*kt];
                uint2 vb = *(const uint2*)&As[(m+8)*48 + ks*16 + 4*kt];
                af[mi][0] = va.x;
                af[mi][1] = vb.x;
                af[mi][2] = va.y;
                af[mi][3] = vb.y;
            }
            #pragma unroll
            for (int nj = 0; nj < 4; nj++) {
                int n = wn + nj*8 + g;
                uint2 u = *(const uint2*)&Bs[n*48 + ks*16 + 4*kt];
                bf[nj][0] = u.x;
                bf[nj][1] = u.y;
            }
            #pragma unroll
            for (int mi = 0; mi < 2; mi++)
                #pragma unroll
                for (int nj = 0; nj < 4; nj++)
                    mma16(acc[mi][nj], af[mi], bf[nj]);
        }
        __syncthreads();
    }

    if (FUSE) {
        // reuse smem: xs tile [64][136] at 0, Wnext [128][136] at +8704 halfs
        __half* xs_s = dynh;
        __half* W_s  = dynh + 8704;
        {
            int n = tid >> 1, off = (tid & 1)*64;
            const __half* wr = Wnext + (size_t)n*AP + off;
            uint32_t wd = s2u(W_s + n*136 + off);
            #pragma unroll
            for (int i = 0; i < 8; i++) cpa16(wd + i*16, wr + i*8);
            asm volatile("cp.async.commit_group;" ::: "memory");
        }
        #pragma unroll
        for (int mi = 0; mi < 2; mi++)
            #pragma unroll
            for (int nj = 0; nj < 4; nj++)
                #pragma unroll
                for (int r = 0; r < 4; r++) {
                    int lr = wm + mi*16 + g + (r>>1)*8;
                    int gn = wn + nj*8 + kt*2 + (r&1);
                    __half hv = __float2half_rn(fast_tanh(acc[mi][nj][r] + __ldg(bias + gn)));
                    xs_s[lr*136 + ilv16(gn)] = hv;
                    int gm = rowBase + lr;
                    if (gm < M)
                        Cg[((size_t)blockIdx.y*FN + gm)*CCH + ilv16(gn)] = hv;
                }
        asm volatile("cp.async.wait_group 0;" ::: "memory");
        __syncthreads();
        // second GEMM: h = xs @ Wnext (K = 128), reuse acc
        #pragma unroll
        for (int mi = 0; mi < 2; mi++)
            #pragma unroll
            for (int nj = 0; nj < 4; nj++)
                #pragma unroll
                for (int r = 0; r < 4; r++) acc[mi][nj][r] = 0.f;
        #pragma unroll
        for (int ks = 0; ks < 8; ks++) {
            uint32_t af[2][4], bf[4][2];
            #pragma unroll
            for (int mi = 0; mi < 2; mi++) {
                int m = wm + mi*16 + g;
                uint2 va = *(const uint2*)&xs_s[m*136     + ks*16 + 4*kt];
                uint2 vb = *(const uint2*)&xs_s[(m+8)*136 + ks*16 + 4*kt];
                af[mi][0] = va.x;
                af[mi][1] = vb.x;
                af[mi][2] = va.y;
                af[mi][3] = vb.y;
            }
            #pragma unroll
            for (int nj = 0; nj < 4; nj++) {
                int n = wn + nj*8 + g;
                uint2 u = *(const uint2*)&W_s[n*136 + ks*16 + 4*kt];
                bf[nj][0] = u.x;
                bf[nj][1] = u.y;
            }
            #pragma unroll
            for (int mi = 0; mi < 2; mi++)
                #pragma unroll
                for (int nj = 0; nj < 4; nj++)
                    mma16(acc[mi][nj], af[mi], bf[nj]);
        }
        #pragma unroll
        for (int mi = 0; mi < 2; mi++)
            #pragma unroll
            for (int nj = 0; nj < 4; nj++)
                #pragma unroll
                for (int r = 0; r < 4; r++) {
                    int j = rowBase + wm + mi*16 + g + (r>>1)*8;   // 0..383 within graph
                    int gn = wn + nj*8 + kt*2 + (r&1);
                    g_hh[((size_t)blockIdx.y*CCH + gn)*AP + ilv16(j)] =
                        __float2half_rn(acc[mi][nj][r]);
                }
        return;
    }

    #pragma unroll
    for (int mi = 0; mi < 2; mi++)
        #pragma unroll
        for (int nj = 0; nj < 4; nj++)
            #pragma unroll
            for (int r = 0; r < 4; r++) {
                int gm = rowBase + wm + mi*16 + g + (r>>1)*8;
                int gn = wn + nj*8 + kt*2 + (r&1);
                float v = acc[mi][nj][r];
                if (MODE == 0) {
                    int b = gm / FN, j = gm - b*FN;
                    g_hh[((size_t)b*CCH + gn)*AP + ilv16(j)] = __float2half_rn(v);
                } else if (MODE == 1) {
                    if (gm < M) {
                        __half* dst = Cg + ((size_t)blockIdx.y*FN + gm)*CCH;
                        dst[ilv16(gn)] = __float2half_rn(fast_tanh(v + __ldg(bias + gn)));
                    }
                } else {
                    atomicAdd(&Cf[(size_t)gm*H1 + bOff + gn], v);
                }
            }
}

// ---------------- legacy tf32 mma.sync GEMM (small MLP layers) ----------------
__global__ __launch_bounds__(256)
void mmak(const float* __restrict__ A, const float* __restrict__ Bm,
          float* __restrict__ C, int M, int N, int K)
{
    __shared__ uint32_t As[2][16][PADK];
    __shared__ uint32_t Bs[2][16][PADK];
    const int tid = threadIdx.x, lane = tid & 31, w = tid >> 5;
    const int wm = (w & 1)*64, wn = (w >> 1)*32;
    const int g = lane >> 2, kt = lane & 3;
    const int rowBase = blockIdx.x*128, colBase = blockIdx.y*128;
    const int aRow = tid >> 1, aCol = (tid & 1)*8;
    const int bRow = tid >> 4, bCol = (tid & 15)*8;
    float acc[4][4][4];
    #pragma unroll
    for (int mi = 0; mi < 4; mi++)
        #pragma unroll
        for (int nj = 0; nj < 4; nj++)
            #pragma unroll
            for (int r = 0; r < 4; r++) acc[mi][nj][r] = 0.f;
    const int gmA = rowBase + aRow;
    float4 pa[2], pb[2];
    auto loadT = [&](int k0) {
        #pragma unroll
        for (int h = 0; h < 2; h++) {
            int gk = k0 + aCol + h*4;
            float4 v = make_float4(0.f,0.f,0.f,0.f);
            if (gmA < M && gk + 3 < K) v = *(const float4*)(A + (size_t)gmA*K + gk);
            pa[h] = v;
        }
        int gk = k0 + bRow;
        #pragma unroll
        for (int h = 0; h < 2; h++) {
            int gn = colBase + bCol + h*4;
            float4 v = make_float4(0.f,0.f,0.f,0.f);
            if (gk < K && gn < N) v = *(const float4*)(Bm + (size_t)gk*N + gn);
            pb[h] = v;
        }
    };
    auto storeT = [&](int buf) {
        #pragma unroll
        for (int h = 0; h < 2; h++) {
            As[buf][aCol+h*4+0][aRow] = f2tf(pa[h].x);
            As[buf][aCol+h*4+1][aRow] = f2tf(pa[h].y);
            As[buf][aCol+h*4+2][aRow] = f2tf(pa[h].z);
            As[buf][aCol+h*4+3][aRow] = f2tf(pa[h].w);
            Bs[buf][bRow][bCol+h*4+0] = f2tf(pb[h].x);
            Bs[buf][bRow][bCol+h*4+1] = f2tf(pb[h].y);
            Bs[buf][bRow][bCol+h*4+2] = f2tf(pb[h].z);
            Bs[buf][bRow][bCol+h*4+3] = f2tf(pb[h].w);
        }
    };
    auto comp = [&](int buf) {
        #pragma unroll
        for (int ks = 0; ks < 2; ks++) {
            uint32_t af[4][4], bf[4][2];
            #pragma unroll
            for (int mi = 0; mi < 4; mi++) {
                int m = wm + mi*16;
                af[mi][0] = As[buf][ks*8+kt  ][m+g  ];
                af[mi][1] = As[buf][ks*8+kt  ][m+g+8];
                af[mi][2] = As[buf][ks*8+kt+4][m+g  ];
                af[mi][3] = As[buf][ks*8+kt+4][m+g+8];
            }
            #pragma unroll
            for (int nj = 0; nj < 4; nj++) {
                int n = wn + nj*8;
                bf[nj][0] = Bs[buf][ks*8+kt  ][n+g];
                bf[nj][1] = Bs[buf][ks*8+kt+4][n+g];
            }
            #pragma unroll
            for (int mi = 0; mi < 4; mi++)
                #pragma unroll
                for (int nj = 0; nj < 4; nj++) mma8(acc[mi][nj], af[mi], bf[nj]);
        }
    };
    const int nIter = (K + 15) >> 4;
    loadT(0); storeT(0); __syncthreads();
    for (int t = 1; t < nIter; t++) {
        loadT(t*16);
        comp((t-1) & 1);
        storeT(t & 1);
        __syncthreads();
    }
    comp((nIter-1) & 1);
    #pragma unroll
    for (int mi = 0; mi < 4; mi++)
        #pragma unroll
        for (int nj = 0; nj < 4; nj++)
            #pragma unroll
            for (int r = 0; r < 4; r++) {
                int gm = rowBase + wm + mi*16 + g + (r>>1)*8;
                int gn = colBase + wn + nj*8 + kt*2 + (r&1);
                if (gm < M && gn < N) C[(size_t)gm*N + gn] = acc[mi][nj][r];
            }
}

// ---------------- BN / pool / head ----------------
__global__ void k_x0_bn(const float* __restrict__ x, const float* __restrict__ g,
                        const float* __restrict__ be, __half* __restrict__ z)
{
    int r = blockIdx.x;
    int c = r + threadIdx.x;
    if (c >= FN) return;
    long j = (long)r*FN - (long)r*(r-1)/2 + (c - r);
    long zi = (j & ~15L) + pl16((int)(j & 15));
    float s = 0.f, ss = 0.f;
    for (int b = 0; b < BGRAPH; b++) {
        float v = x[((size_t)(b*FN + r))*FN + c];
        s += v; ss += v*v;
    }
    float m = s*(1.f/BGRAPH);
    float var = ss*(1.f/BGRAPH) - m*m;
    float sc = rsqrtf(var + EPSV)*g[j];
    float bb = be[j];
    for (int b = 0; b < BGRAPH; b++) {
        float v = x[((size_t)(b*FN + r))*FN + c];
        z[(size_t)b*ZP + zi] = __float2half_rn((v - m)*sc + bb);
    }
}
__global__ void k_pool(const __half* __restrict__ xs, float* __restrict__ hp, int l)
{
    int b = blockIdx.x, k = threadIdx.x;
    const __half* base = xs + (size_t)b*FN*CCH + k;
    float s0=0.f, s1=0.f, s2=0.f, s3=0.f;
    #pragma unroll 1
    for (int n = 0; n < FN; n += 4) {
        s0 += __half2float(base[(size_t)(n+0)*CCH]);
        s1 += __half2float(base[(size_t)(n+1)*CCH]);
        s2 += __half2float(base[(size_t)(n+2)*CCH]);
        s3 += __half2float(base[(size_t)(n+3)*CCH]);
    }
    int oc = (k & ~15) + orig16p(k & 15);
    hp[b*384 + l*CCH + oc] = (s0+s1+s2+s3)*(1.0f/FN);
}
__global__ void k_bn_pool(const float* __restrict__ hp, const float* __restrict__ g,
                          const float* __restrict__ be, __half* __restrict__ z)
{
    int j = blockIdx.x*blockDim.x + threadIdx.x;
    if (j >= ZP - TRI) return;
    long cg2 = (long)TRI + j;
    long zi = (cg2 & ~15L) + pl16((int)(cg2 & 15));
    if (j >= 384) {
        for (int b = 0; b < BGRAPH; b++) z[(size_t)b*ZP + zi] = __half(0.f);
        return;
    }
    float s = 0.f, ss = 0.f;
    for (int b = 0; b < BGRAPH; b++) { float v = hp[b*384 + j]; s += v; ss += v*v; }
    float m = s*(1.f/BGRAPH);
    float var = ss*(1.f/BGRAPH) - m*m;
    float sc = rsqrtf(var + EPSV)*g[j];
    float bb = be[j];
    for (int b = 0; b < BGRAPH; b++)
        z[(size_t)b*ZP + zi] = __float2half_rn((hp[b*384 + j] - m)*sc + bb);
}
__global__ void k_bn_relu(const float* __restrict__ X, const float* __restrict__ bias,
                          const float* __restrict__ gam, const float* __restrict__ bet,
                          float* __restrict__ Y, int ncols)
{
    int col = blockIdx.x, t = threadIdx.x;
    float v = X[t*ncols + col] + bias[col];
    float s = v, ss = v*v;
    #pragma unroll
    for (int o = 16; o > 0; o >>= 1) {
        s  += __shfl_down_sync(0xffffffffu, s,  o);
        ss += __shfl_down_sync(0xffffffffu, ss, o);
    }
    __shared__ float ws[4], wss[4];
    __shared__ float sm, sscale;
    int wid = t >> 5, lane = t & 31;
    if (lane == 0) { ws[wid] = s; wss[wid] = ss; }
    __syncthreads();
    if (t == 0) {
        float S = ws[0]+ws[1]+ws[2]+ws[3];
        float SS = wss[0]+wss[1]+wss[2]+wss[3];
        float m = S*(1.f/BGRAPH);
        sm = m; sscale = rsqrtf(SS*(1.f/BGRAPH) - m*m + EPSV);
    }
    __syncthreads();
    float o = (v - sm)*sscale*gam[col] + bet[col];
    Y[t*ncols + col] = fmaxf(o, 0.f);
}
__global__ void k_head(const float* __restrict__ a3, const float* __restrict__ W4,
                       const float* __restrict__ b4, float* __restrict__ out)
{
    int b = blockIdx.x, lane = threadIdx.x;
    float s0 = 0.f, s1 = 0.f;
    for (int i = lane; i < H2; i += 32) {
        float v = a3[b*H2 + i];
        s0 = fmaf(v, W4[i*2+0], s0);
        s1 = fmaf(v, W4[i*2+1], s1);
    }
    #pragma unroll
    for (int o = 16; o > 0; o >>= 1) {
        s0 += __shfl_down_sync(0xffffffffu, s0, o);
        s1 += __shfl_down_sync(0xffffffffu, s1, o);
    }
    if (lane == 0) {
        float l0 = s0 + b4[0], l1 = s1 + b4[1];
        float m = fmaxf(l0, l1);
        float lse = m + logf(expf(l0-m) + expf(l1-m));
        out[b*2+0] = l0 - lse;
        out[b*2+1] = l1 - lse;
    }
}

// ---------------- launch ----------------
extern "C" void kernel_launch(void* const* d_in, const int* in_sizes, int n_in,
                              void* d_out, int out_size)
{
    const float* x    = (const float*)d_in[0];
    const int*   esrc = (const int*)d_in[1];
    const int*   edst = (const int*)d_in[2];
    const float* Wc1  = (const float*)d_in[4];
    const float* bc1  = (const float*)d_in[5];
    const float* Wc2  = (const float*)d_in[6];
    const float* bc2  = (const float*)d_in[7];
    const float* Wc3  = (const float*)d_in[8];
    const float* bc3  = (const float*)d_in[9];
    const float* bn_g = (const float*)d_in[10];
    const float* bn_b = (const float*)d_in[11];
    const float* bnh_g= (const float*)d_in[12];
    const float* bnh_b= (const float*)d_in[13];
    const float* W1   = (const float*)d_in[14];
    const float* b1   = (const float*)d_in[15];
    const float* g1   = (const float*)d_in[16];
    const float* be1  = (const float*)d_in[17];
    const float* W2   = (const float*)d_in[18];
    const float* b2   = (const float*)d_in[19];
    const float* g2   = (const float*)d_in[20];
    const float* be2  = (const float*)d_in[21];
    const float* W3   = (const float*)d_in[22];
    const float* b3   = (const float*)d_in[23];
    const float* g3   = (const float*)d_in[24];
    const float* be3  = (const float*)d_in[25];
    const float* W4   = (const float*)d_in[26];
    const float* b4   = (const float*)d_in[27];
    float* out = (float*)d_out;

    const int DSMH = 3*9216*2;
    cudaFuncSetAttribute((const void*)gkh<0,0>, cudaFuncAttributeMaxDynamicSharedMemorySize, DSMH);
    cudaFuncSetAttribute((const void*)gkh<1,0>, cudaFuncAttributeMaxDynamicSharedMemorySize, DSMH);
    cudaFuncSetAttribute((const void*)gkh<1,1>, cudaFuncAttributeMaxDynamicSharedMemorySize, DSMH);
    cudaFuncSetAttribute((const void*)gkh<2,0>, cudaFuncAttributeMaxDynamicSharedMemorySize, DSMH);

    void *pDinv, *pAh, *pXh, *pHh, *pX1, *pX2, *pX3, *pZh, *pW1h, *pHp, *pA1, *pA2, *pA3, *pWh;
    cudaGetSymbolAddress(&pDinv, g_dinv);
    cudaGetSymbolAddress(&pAh,  g_Ah);
    cudaGetSymbolAddress(&pXh,  g_xh);
    cudaGetSymbolAddress(&pHh,  g_hh);
    cudaGetSymbolAddress(&pX1,  g_x1h);
    cudaGetSymbolAddress(&pX2,  g_x2h);
    cudaGetSymbolAddress(&pX3,  g_x3h);
    cudaGetSymbolAddress(&pZh,  g_zh);
    cudaGetSymbolAddress(&pW1h, g_w1h);
    cudaGetSymbolAddress(&pHp,  g_hpool);
    cudaGetSymbolAddress(&pA1,  g_a1);
    cudaGetSymbolAddress(&pA2,  g_a2);
    cudaGetSymbolAddress(&pA3,  g_a3);
    cudaGetSymbolAddress(&pWh,  g_wh);

    const __half* wh = (const __half*)pWh;
    const __half* xh = (const __half*)pXh;
    const __half* Ah = (const __half*)pAh;
    const __half* hh = (const __half*)pHh;
    const __half* zh = (const __half*)pZh;
    const __half* w1h = (const __half*)pW1h;

    cudaStream_t s1, s2;
    cudaStreamCreateWithFlags(&s1, cudaStreamNonBlocking);
    cudaStreamCreateWithFlags(&s2, cudaStreamNonBlocking);
    cudaEvent_t eFork, eAdj, eZ, eX1, eX2, ePool;
    cudaEventCreateWithFlags(&eFork, cudaEventDisableTiming);
    cudaEventCreateWithFlags(&eAdj,  cudaEventDisableTiming);
    cudaEventCreateWithFlags(&eZ,    cudaEventDisableTiming);
    cudaEventCreateWithFlags(&eX1,   cudaEventDisableTiming);
    cudaEventCreateWithFlags(&eX2,   cudaEventDisableTiming);
    cudaEventCreateWithFlags(&ePool, cudaEventDisableTiming);

    cudaEventRecord(eFork, 0);
    cudaStreamWaitEvent(s1, eFork, 0);
    cudaStreamWaitEvent(s2, eFork, 0);

    // s1: adjacency chain, then pools for layers 1-2
    cudaMemsetAsync(pDinv, 0, (size_t)NNODE*4, s1);
    cudaMemsetAsync(pAh, 0, (size_t)BGRAPH*AP*AP*2, s1);
    k_count_deg<<<(NEDGE+255)/256, 256, 0, s1>>>(edst);
    k_make_dinv<<<(NNODE+255)/256, 256, 0, s1>>>();
    k_build<<<(NEDGE+NNODE+255)/256, 256, 0, s1>>>(esrc, edst);
    cudaEventRecord(eAdj, s1);

    // s2: W1 conversion + triu BN + early zW1 (cols < 64512)
    k_w1h<<<dim3(ZP/64, H1/32), 256, 0, s2>>>(W1);
    k_x0_bn<<<FN, 384, 0, s2>>>(x, bn_g, bn_b, (__half*)pZh);
    cudaMemsetAsync(pA1, 0, (size_t)BGRAPH*H1*4, s2);
    gkh<2,0><<<dim3(2,4,63), 256, DSMH, s2>>>(zh, w1h, nullptr, nullptr, (float*)pA1,
                                              nullptr, ZP, ZP, BGRAPH, 1024, 0);
    cudaEventRecord(eZ, s2);

    // s0: XW1 then fused AH chain
    cudaMemsetAsync(pHh, 0, (size_t)BGRAPH*CCH*AP*2, 0);
    k_prep<<<(3*CCH*(AP/16)+255)/256, 256>>>(Wc1, Wc2, Wc3);
    k_xh<<<(NNODE*(AP/16)+255)/256, 256>>>(x);
    gkh<0,0><<<dim3(720,1), 256, DSMH>>>(xh, wh, nullptr, nullptr, nullptr, nullptr,
                                         AP, AP, NNODE, AP, 0);
    cudaStreamWaitEvent(0, eAdj, 0);
    gkh<1,1><<<dim3(6,BGRAPH), 256, DSMH>>>(Ah, hh, bc1, (__half*)pX1, nullptr,
                                            wh + (size_t)CCH*AP, AP, AP, FN, AP, 0);
    cudaEventRecord(eX1, 0);
    gkh<1,1><<<dim3(6,BGRAPH), 256, DSMH>>>(Ah, hh, bc2, (__half*)pX2, nullptr,
                                            wh + (size_t)2*CCH*AP, AP, AP, FN, AP, 0);
    cudaEventRecord(eX2, 0);
    gkh<1,0><<<dim3(6,BGRAPH), 256, DSMH>>>(Ah, hh, bc3, (__half*)pX3, nullptr,
                                            nullptr, AP, AP, FN, AP, 0);

    // s1: pools for layers 1-2 overlap AH2/AH3
    cudaStreamWaitEvent(s1, eX1, 0);
    k_pool<<<BGRAPH, CCH, 0, s1>>>((const __half*)pX1, (float*)pHp, 0);
    cudaStreamWaitEvent(s1, eX2, 0);
    k_pool<<<BGRAPH, CCH, 0, s1>>>((const __half*)pX2, (float*)pHp, 1);
    cudaEventRecord(ePool, s1);

    // s0: pool3 + BN + last zW1 split + MLP
    k_pool<<<BGRAPH, CCH>>>((const __half*)pX3, (float*)pHp, 2);
    cudaStreamWaitEvent(0, ePool, 0);
    k_bn_pool<<<1, 1024>>>((const float*)pHp, bnh_g, bnh_b, (__half*)pZh);
    cudaStreamWaitEvent(0, eZ, 0);
    gkh<2,0><<<dim3(2,4,1), 256, DSMH>>>(zh, w1h, nullptr, nullptr, (float*)pA1,
                                         nullptr, ZP, ZP, BGRAPH, 1024, 64512);
    k_bn_relu<<<H1, 128>>>((const float*)pA1, b1, g1, be1, (float*)pA1, H1);
    mmak<<<dim3(1,2), 256>>>((const float*)pA1, W2, (float*)pA2, BGRAPH, H2, H1);
    k_bn_relu<<<H2, 128>>>((const float*)pA2, b2, g2, be2, (float*)pA2, H2);
    mmak<<<dim3(1,2), 256>>>((const float*)pA2, W3, (float*)pA3, BGRAPH, H2, H2);
    k_bn_relu<<<H2, 128>>>((const float*)pA3, b3, g3, be3, (float*)pA3, H2);
    k_head<<<BGRAPH, 32>>>((const float*)pA3, W4, b4, out);

    cudaEventDestroy(eFork);
    cudaEventDestroy(eAdj);
    cudaEventDestroy(eZ);
    cudaEventDestroy(eX1);
    cudaEventDestroy(eX2);
    cudaEventDestroy(ePool);
    cudaStreamDestroy(s1);
    cudaStreamDestroy(s2);
}

// round 16
// speedup vs baseline: 1.1981x; 1.0273x over previous
#include <cuda_runtime.h>
#include <cuda_fp16.h>
#include <math.h>
#include <stdint.h>

#define FN 360
#define BGRAPH 128
#define NNODE (FN*BGRAPH)
#define NEDGE 1000000
#define CCH 128
#define TRI 64980
#define D1 65364
#define ZP 65536
#define H1 512
#define H2 256
#define EPSV 1e-5f
#define PADK 136
#define AP 384

// ---------------- scratch ----------------
__device__ __align__(16) float  g_dinv[NNODE];
__device__ __align__(16) __half g_Ah[(size_t)BGRAPH*AP*AP];
__device__ __align__(16) __half g_xh[(size_t)NNODE*AP];
__device__ __align__(16) __half g_wh[(size_t)3*CCH*AP];
__device__ __align__(16) __half g_hh[(size_t)BGRAPH*CCH*AP];
__device__ __align__(16) __half g_x1h[(size_t)NNODE*CCH];
__device__ __align__(16) __half g_x2h[(size_t)NNODE*CCH];
__device__ __align__(16) __half g_x3h[(size_t)NNODE*CCH];
__device__ __align__(16) __half g_zh[(size_t)BGRAPH*ZP];
__device__ __align__(16) __half g_w1h[(size_t)H1*ZP];
__device__ __align__(16) float  g_hpool[BGRAPH*384];
__device__ __align__(16) float  g_a1[BGRAPH*H1];
__device__ __align__(16) float  g_a2[BGRAPH*H2];
__device__ __align__(16) float  g_a3[BGRAPH*H2];

// ---------------- helpers ----------------
__device__ __forceinline__ uint32_t f2tf(float f) {
    uint32_t u; asm("cvt.rna.tf32.f32 %0, %1;" : "=r"(u) : "f"(f)); return u;
}
__device__ __forceinline__ int pl16(int j)  { int p=j>>1, b=j&1; return ((p&3)<<2)|(((p>>2)&1)<<1)|b; }
__device__ __forceinline__ int ilv16(int c) { return (c & ~15) + pl16(c & 15); }
__device__ __forceinline__ int orig16p(int q){ int b=q&1, t=(q>>1)&7; int p=((t&1)<<2)|(t>>1); return 2*p+b; }
__device__ __forceinline__ float fast_tanh(float x) {
    float e = __expf(2.0f*x);
    return 1.0f - __fdividef(2.0f, e + 1.0f);
}
__device__ __forceinline__ uint32_t s2u(const void* p) {
    uint32_t a;
    asm("{ .reg .u64 t; cvta.to.shared.u64 t, %1; cvt.u32.u64 %0, t; }" : "=r"(a) : "l"(p));
    return a;
}
__device__ __forceinline__ void cpa16(uint32_t d, const void* g) {
    asm volatile("cp.async.cg.shared.global [%0], [%1], 16;" :: "r"(d), "l"(g));
}
__device__ __forceinline__ void mma8(float* c, const uint32_t* a, const uint32_t* b) {
    asm volatile("mma.sync.aligned.m16n8k8.row.col.f32.tf32.tf32.f32 "
        "{%0,%1,%2,%3}, {%4,%5,%6,%7}, {%8,%9}, {%0,%1,%2,%3};"
        : "+f"(c[0]), "+f"(c[1]), "+f"(c[2]), "+f"(c[3])
        : "r"(a[0]), "r"(a[1]), "r"(a[2]), "r"(a[3]), "r"(b[0]), "r"(b[1]));
}
__device__ __forceinline__ void mma16(float* c, const uint32_t* a, const uint32_t* b) {
    asm volatile("mma.sync.aligned.m16n8k16.row.col.f32.f16.f16.f32 "
        "{%0,%1,%2,%3}, {%4,%5,%6,%7}, {%8,%9}, {%0,%1,%2,%3};"
        : "+f"(c[0]), "+f"(c[1]), "+f"(c[2]), "+f"(c[3])
        : "r"(a[0]), "r"(a[1]), "r"(a[2]), "r"(a[3]), "r"(b[0]), "r"(b[1]));
}

// ---------------- prep ----------------
__global__ void k_prep(const float* __restrict__ Wc1, const float* __restrict__ Wc2,
                       const float* __restrict__ Wc3) {
    int i = blockIdx.x*blockDim.x + threadIdx.x;
    if (i >= 3*CCH*(AP/16)) return;
    int w = i / (CCH*(AP/16));
    int r = (i / (AP/16)) % CCH;
    int grp = i % (AP/16);
    const float* W = (w==0) ? Wc1 : (w==1) ? Wc2 : Wc3;
    int KW = (w==0) ? FN : CCH;
    __align__(16) __half o[16];
    #pragma unroll
    for (int j = 0; j < 16; j++) {
        int k = grp*16 + j;
        o[pl16(j)] = (k < KW) ? __float2half_rn(W[k*CCH + r]) : __half(0.f);
    }
    __half* dst = g_wh + ((size_t)(w*CCH + r))*AP + grp*16;
    ((uint4*)dst)[0] = ((uint4*)o)[0];
    ((uint4*)dst)[1] = ((uint4*)o)[1];
}
__global__ void k_xh(const float* __restrict__ x) {
    int i = blockIdx.x*blockDim.x + threadIdx.x;
    if (i >= NNODE*(AP/16)) return;
    int n = i / (AP/16), grp = i % (AP/16);
    __align__(16) __half o[16];
    #pragma unroll
    for (int j = 0; j < 16; j++) {
        int k = grp*16 + j;
        o[pl16(j)] = (k < FN) ? __float2half_rn(x[(size_t)n*FN + k]) : __half(0.f);
    }
    __half* dst = g_xh + (size_t)n*AP + grp*16;
    ((uint4*)dst)[0] = ((uint4*)o)[0];
    ((uint4*)dst)[1] = ((uint4*)o)[1];
}
__global__ void k_w1h(const float* __restrict__ W1) {
    __shared__ float s[64][33];
    int k0 = blockIdx.x * 64;
    int n0 = blockIdx.y * 32;
    int t = threadIdx.x;
    int nl = t & 31, kb = t >> 5;
    #pragma unroll
    for (int i = 0; i < 8; i++) {
        int k = k0 + kb*8 + i;
        s[kb*8 + i][nl] = (k < D1) ? W1[(size_t)k*H1 + n0 + nl] : 0.f;
    }
    __syncthreads();
    if (t < 128) {
        int nl2 = t >> 2, gl = t & 3;
        __align__(16) __half o[16];
        #pragma unroll
        for (int j = 0; j < 16; j++)
            o[pl16(j)] = __float2half_rn(s[gl*16 + j][nl2]);
        __half* dst = g_w1h + (size_t)(n0 + nl2)*ZP + k0 + gl*16;
        ((uint4*)dst)[0] = ((uint4*)o)[0];
        ((uint4*)dst)[1] = ((uint4*)o)[1];
    }
}
__global__ void k_count_deg(const int* __restrict__ dst) {
    int i = blockIdx.x*blockDim.x + threadIdx.x;
    if (i < NEDGE) atomicAdd(&g_dinv[dst[i]], 1.0f);
}
__global__ void k_make_dinv() {
    int i = blockIdx.x*blockDim.x + threadIdx.x;
    if (i < NNODE) g_dinv[i] = rsqrtf(g_dinv[i] + 1.0f);
}
__global__ void k_build(const int* __restrict__ src, const int* __restrict__ dst) {
    int i = blockIdx.x*blockDim.x + threadIdx.x;
    if (i < NEDGE) {
        int d = dst[i], s = src[i];
        int b = d / FN, r = d - b*FN, c = s - b*FN;
        atomicAdd(&g_Ah[((size_t)b*AP + r)*AP + ilv16(c)],
                  __float2half_rn(g_dinv[s]*g_dinv[d]));
    } else if (i < NEDGE + NNODE) {
        int n = i - NEDGE, b = n / FN, r = n - b*FN;
        atomicAdd(&g_Ah[((size_t)b*AP + r)*AP + ilv16(r)],
                  __float2half_rn(g_dinv[n]*g_dinv[n]));
    }
}

// ---------------- fp16 HMMA GEMM, 64x128 tile, BK=32, 4-stage cp.async -------
// MODE 0: XW -> g_hh. MODE 1: AH -> xs (FUSE=1 also h_next = xs@Wnext).
// MODE 2: zW1 split-K, fp32 atomicAdd.
template<int MODE, int FUSE>
__global__ __launch_bounds__(256, 3)
void gkh(const __half* __restrict__ Ag, const __half* __restrict__ Bg,
         const float* __restrict__ bias, __half* __restrict__ Cg,
         float* __restrict__ Cf, const __half* __restrict__ Wnext,
         int lda, int ldb, int M, int K, int koff)
{
    extern __shared__ __align__(16) __half dynh[];
    const int STG = 9216;
    const int tid = threadIdx.x, lane = tid & 31, w = tid >> 5;
    const int wm = (w & 1)*32, wn = (w >> 1)*32;
    const int g = lane >> 2, kt = lane & 3;
    const int rowBase = blockIdx.x*64;
    const int bOff = (MODE == 2) ? blockIdx.y*128 : 0;

    if (MODE == 1) {
        Ag += (size_t)blockIdx.y * AP * AP;
        Bg += (size_t)blockIdx.y * CCH * AP;
    }
    const int kbeg = (MODE == 2) ? (koff + blockIdx.z*1024) : 0;
    const int am = tid >> 2;
    const int ak = (tid & 3) * 8;
    const int bm = tid >> 1;
    const int bk = (tid & 1) * 16;

    auto load_chunk = [&](int c, int stg) {
        int k0 = kbeg + c*32;
        __half* As = dynh + stg*STG;
        __half* Bs = As + 3072;
        const __half* ar = Ag + (size_t)(rowBase + am)*lda + k0 + ak;
        cpa16(s2u(As + am*48 + ak), ar);
        const __half* br = Bg + (size_t)(bOff + bm)*ldb + k0 + bk;
        uint32_t bd = s2u(Bs + bm*48 + bk);
        cpa16(bd,      br);
        cpa16(bd + 16, br + 8);
        asm volatile("cp.async.commit_group;" ::: "memory");
    };

    float acc[2][4][4];
    #pragma unroll
    for (int mi = 0; mi < 2; mi++)
        #pragma unroll
        for (int nj = 0; nj < 4; nj++)
            #pragma unroll
            for (int r = 0; r < 4; r++) acc[mi][nj][r] = 0.f;

    const int nch = K >> 5;
    load_chunk(0, 0);
    load_chunk(1, 1);
    load_chunk(2, 2);
    for (int c = 0; c < nch; c++) {
        int buf = c & 3;
        if (c + 3 < nch) {
            load_chunk(c + 3, (c + 3) & 3);
            asm volatile("cp.async.wait_group 3;" ::: "memory");
        } else if (c + 2 < nch) {
            asm volatile("cp.async.wait_group 2;" ::: "memory");
        } else if (c + 1 < nch) {
            asm volatile("cp.async.wait_group 1;" ::: "memory");
        } else {
            asm volatile("cp.async.wait_group 0;" ::: "memory");
        }
        __syncthreads();
        const __half* As = dynh + buf*STG;
        const __half* Bs = As + 3072;
        #pragma unroll
        for (int ks = 0; ks < 2; ks++) {
            uint32_t af[2][4], bf[4][2];
            #pragma unroll
            for (int mi = 0; mi < 2; mi++) {
                int m = wm + mi*16 + g;
                uint2 va = *(const uint2*)&As[m*48     + ks*16 + 4*kt];
                uint2 vb = *(const uint2*)&As[(m+8)*48 + ks*16 + 4*kt];
                af[mi][0] = va.x;
                af[mi][1] = vb.x;
                af[mi][2] = va.y;
                af[mi][3] = vb.y;
            }
            #pragma unroll
            for (int nj = 0; nj < 4; nj++) {
                int n = wn + nj*8 + g;
                uint2 u = *(const uint2*)&Bs[n*48 + ks*16 + 4*kt];
                bf[nj][0] = u.x;
                bf[nj][1] = u.y;
            }
            #pragma unroll
            for (int mi = 0; mi < 2; mi++)
                #pragma unroll
                for (int nj = 0; nj < 4; nj++)
                    mma16(acc[mi][nj], af[mi], bf[nj]);
        }
        __syncthreads();
    }

    if (FUSE) {
        __half* xs_s = dynh;
        __half* W_s  = dynh + 8704;
        {
            int n = tid >> 1, off = (tid & 1)*64;
            const __half* wr = Wnext + (size_t)n*AP + off;
            uint32_t wd = s2u(W_s + n*136 + off);
            #pragma unroll
            for (int i = 0; i < 8; i++) cpa16(wd + i*16, wr + i*8);
            asm volatile("cp.async.commit_group;" ::: "memory");
        }
        #pragma unroll
        for (int mi = 0; mi < 2; mi++)
            #pragma unroll
            for (int nj = 0; nj < 4; nj++)
                #pragma unroll
                for (int r = 0; r < 4; r++) {
                    int lr = wm + mi*16 + g + (r>>1)*8;
                    int gn = wn + nj*8 + kt*2 + (r&1);
                    __half hv = __float2half_rn(fast_tanh(acc[mi][nj][r] + __ldg(bias + gn)));
                    xs_s[lr*136 + ilv16(gn)] = hv;
                    int gm = rowBase + lr;
                    if (gm < M)
                        Cg[((size_t)blockIdx.y*FN + gm)*CCH + ilv16(gn)] = hv;
                }
        asm volatile("cp.async.wait_group 0;" ::: "memory");
        __syncthreads();
        #pragma unroll
        for (int mi = 0; mi < 2; mi++)
            #pragma unroll
            for (int nj = 0; nj < 4; nj++)
                #pragma unroll
                for (int r = 0; r < 4; r++) acc[mi][nj][r] = 0.f;
        #pragma unroll
        for (int ks = 0; ks < 8; ks++) {
            uint32_t af[2][4], bf[4][2];
            #pragma unroll
            for (int mi = 0; mi < 2; mi++) {
                int m = wm + mi*16 + g;
                uint2 va = *(const uint2*)&xs_s[m*136     + ks*16 + 4*kt];
                uint2 vb = *(const uint2*)&xs_s[(m+8)*136 + ks*16 + 4*kt];
                af[mi][0] = va.x;
                af[mi][1] = vb.x;
                af[mi][2] = va.y;
                af[mi][3] = vb.y;
            }
            #pragma unroll
            for (int nj = 0; nj < 4; nj++) {
                int n = wn + nj*8 + g;
                uint2 u = *(const uint2*)&W_s[n*136 + ks*16 + 4*kt];
                bf[nj][0] = u.x;
                bf[nj][1] = u.y;
            }
            #pragma unroll
            for (int mi = 0; mi < 2; mi++)
                #pragma unroll
                for (int nj = 0; nj < 4; nj++)
                    mma16(acc[mi][nj], af[mi], bf[nj]);
        }
        #pragma unroll
        for (int mi = 0; mi < 2; mi++)
            #pragma unroll
            for (int nj = 0; nj < 4; nj++)
                #pragma unroll
                for (int r = 0; r < 4; r++) {
                    int j = rowBase + wm + mi*16 + g + (r>>1)*8;
                    int gn = wn + nj*8 + kt*2 + (r&1);
                    g_hh[((size_t)blockIdx.y*CCH + gn)*AP + ilv16(j)] =
                        __float2half_rn(acc[mi][nj][r]);
                }
        return;
    }

    #pragma unroll
    for (int mi = 0; mi < 2; mi++)
        #pragma unroll
        for (int nj = 0; nj < 4; nj++)
            #pragma unroll
            for (int r = 0; r < 4; r++) {
                int gm = rowBase + wm + mi*16 + g + (r>>1)*8;
                int gn = wn + nj*8 + kt*2 + (r&1);
                float v = acc[mi][nj][r];
                if (MODE == 0) {
                    int b = gm / FN, j = gm - b*FN;
                    g_hh[((size_t)b*CCH + gn)*AP + ilv16(j)] = __float2half_rn(v);
                } else if (MODE == 1) {
                    if (gm < M) {
                        __half* dst = Cg + ((size_t)blockIdx.y*FN + gm)*CCH;
                        dst[ilv16(gn)] = __float2half_rn(fast_tanh(v + __ldg(bias + gn)));
                    }
                } else {
                    atomicAdd(&Cf[(size_t)gm*H1 + bOff + gn], v);
                }
            }
}

// ---------------- tf32 GEMM with fused input-BN+ReLU (MLP layers) ------------
// C[M,N] = BNrelu(A)[M,K] @ B[K,N]. BN stats per K-column over M=128 rows
// (bias before BN cancels in mean subtraction, so no bias term needed).
__global__ __launch_bounds__(256)
void mmakBN(const float* __restrict__ A, const float* __restrict__ Bm,
            const float* __restrict__ gam, const float* __restrict__ bet,
            float* __restrict__ C, int M, int N, int K)
{
    __shared__ float cSc[512], cSh[512];
    __shared__ uint32_t As[2][16][PADK];
    __shared__ uint32_t Bs[2][16][PADK];
    const int tid = threadIdx.x, lane = tid & 31, w = tid >> 5;
    const int wm = (w & 1)*64, wn = (w >> 1)*32;
    const int g = lane >> 2, kt = lane & 3;
    const int rowBase = blockIdx.x*128, colBase = blockIdx.y*128;
    const int aRow = tid >> 1, aCol = (tid & 1)*8;
    const int bRow = tid >> 4, bCol = (tid & 15)*8;

    for (int col = tid; col < K; col += 256) {
        float s = 0.f, ss = 0.f;
        for (int r = 0; r < BGRAPH; r++) {
            float v = A[(size_t)r*K + col];
            s += v; ss += v*v;
        }
        float mu = s*(1.f/BGRAPH);
        float rs = rsqrtf(ss*(1.f/BGRAPH) - mu*mu + EPSV)*gam[col];
        cSc[col] = rs;
        cSh[col] = bet[col] - mu*rs;
    }
    __syncthreads();

    float acc[4][4][4];
    #pragma unroll
    for (int mi = 0; mi < 4; mi++)
        #pragma unroll
        for (int nj = 0; nj < 4; nj++)
            #pragma unroll
            for (int r = 0; r < 4; r++) acc[mi][nj][r] = 0.f;
    const int gmA = rowBase + aRow;
    float4 pa[2], pb[2];
    auto loadT = [&](int k0) {
        #pragma unroll
        for (int h = 0; h < 2; h++) {
            int gk = k0 + aCol + h*4;
            float4 v = make_float4(0.f,0.f,0.f,0.f);
            if (gmA < M && gk + 3 < K) {
                v = *(const float4*)(A + (size_t)gmA*K + gk);
                v.x = fmaxf(v.x*cSc[gk+0] + cSh[gk+0], 0.f);
                v.y = fmaxf(v.y*cSc[gk+1] + cSh[gk+1], 0.f);
                v.z = fmaxf(v.z*cSc[gk+2] + cSh[gk+2], 0.f);
                v.w = fmaxf(v.w*cSc[gk+3] + cSh[gk+3], 0.f);
            }
            pa[h] = v;
        }
        int gk = k0 + bRow;
        #pragma unroll
        for (int h = 0; h < 2; h++) {
            int gn = colBase + bCol + h*4;
            float4 v = make_float4(0.f,0.f,0.f,0.f);
            if (gk < K && gn < N) v = *(const float4*)(Bm + (size_t)gk*N + gn);
            pb[h] = v;
        }
    };
    auto storeT = [&](int buf) {
        #pragma unroll
        for (int h = 0; h < 2; h++) {
            As[buf][aCol+h*4+0][aRow] = f2tf(pa[h].x);
            As[buf][aCol+h*4+1][aRow] = f2tf(pa[h].y);
            As[buf][aCol+h*4+2][aRow] = f2tf(pa[h].z);
            As[buf][aCol+h*4+3][aRow] = f2tf(pa[h].w);
            Bs[buf][bRow][bCol+h*4+0] = f2tf(pb[h].x);
            Bs[buf][bRow][bCol+h*4+1] = f2tf(pb[h].y);
            Bs[buf][bRow][bCol+h*4+2] = f2tf(pb[h].z);
            Bs[buf][bRow][bCol+h*4+3] = f2tf(pb[h].w);
        }
    };
    auto comp = [&](int buf) {
        #pragma unroll
        for (int ks = 0; ks < 2; ks++) {
            uint32_t af[4][4], bf[4][2];
            #pragma unroll
            for (int mi = 0; mi < 4; mi++) {
                int m = wm + mi*16;
                af[mi][0] = As[buf][ks*8+kt  ][m+g  ];
                af[mi][1] = As[buf][ks*8+kt  ][m+g+8];
                af[mi][2] = As[buf][ks*8+kt+4][m+g  ];
                af[mi][3] = As[buf][ks*8+kt+4][m+g+8];
            }
            #pragma unroll
            for (int nj = 0; nj < 4; nj++) {
                int n = wn + nj*8;
                bf[nj][0] = Bs[buf][ks*8+kt  ][n+g];
                bf[nj][1] = Bs[buf][ks*8+kt+4][n+g];
            }
            #pragma unroll
            for (int mi = 0; mi < 4; mi++)
                #pragma unroll
                for (int nj = 0; nj < 4; nj++) mma8(acc[mi][nj], af[mi], bf[nj]);
        }
    };
    const int nIter = (K + 15) >> 4;
    loadT(0); storeT(0); __syncthreads();
    for (int t = 1; t < nIter; t++) {
        loadT(t*16);
        comp((t-1) & 1);
        storeT(t & 1);
        __syncthreads();
    }
    comp((nIter-1) & 1);
    #pragma unroll
    for (int mi = 0; mi < 4; mi++)
        #pragma unroll
        for (int nj = 0; nj < 4; nj++)
            #pragma unroll
            for (int r = 0; r < 4; r++) {
                int gm = rowBase + wm + mi*16 + g + (r>>1)*8;
                int gn = colBase + wn + nj*8 + kt*2 + (r&1);
                if (gm < M && gn < N) C[(size_t)gm*N + gn] = acc[mi][nj][r];
            }
}

// ---------------- BN / pool / head ----------------
__global__ void k_x0_bn(const float* __restrict__ x, const float* __restrict__ g,
                        const float* __restrict__ be, __half* __restrict__ z)
{
    int r = blockIdx.x;
    int c = r + threadIdx.x;
    if (c >= FN) return;
    long j = (long)r*FN - (long)r*(r-1)/2 + (c - r);
    long zi = (j & ~15L) + pl16((int)(j & 15));
    float s = 0.f, ss = 0.f;
    for (int b = 0; b < BGRAPH; b++) {
        float v = x[((size_t)(b*FN + r))*FN + c];
        s += v; ss += v*v;
    }
    float m = s*(1.f/BGRAPH);
    float var = ss*(1.f/BGRAPH) - m*m;
    float sc = rsqrtf(var + EPSV)*g[j];
    float bb = be[j];
    for (int b = 0; b < BGRAPH; b++) {
        float v = x[((size_t)(b*FN + r))*FN + c];
        z[(size_t)b*ZP + zi] = __float2half_rn((v - m)*sc + bb);
    }
}
__global__ void k_pool(const __half* __restrict__ xs, float* __restrict__ hp, int l)
{
    int b = blockIdx.x, k = threadIdx.x;
    const __half* base = xs + (size_t)b*FN*CCH + k;
    float s0=0.f, s1=0.f, s2=0.f, s3=0.f;
    #pragma unroll 1
    for (int n = 0; n < FN; n += 4) {
        s0 += __half2float(base[(size_t)(n+0)*CCH]);
        s1 += __half2float(base[(size_t)(n+1)*CCH]);
        s2 += __half2float(base[(size_t)(n+2)*CCH]);
        s3 += __half2float(base[(size_t)(n+3)*CCH]);
    }
    int oc = (k & ~15) + orig16p(k & 15);
    hp[b*384 + l*CCH + oc] = (s0+s1+s2+s3)*(1.0f/FN);
}
__global__ void k_bn_pool(const float* __restrict__ hp, const float* __restrict__ g,
                          const float* __restrict__ be, __half* __restrict__ z)
{
    int j = blockIdx.x*blockDim.x + threadIdx.x;
    if (j >= ZP - TRI) return;
    long cg2 = (long)TRI + j;
    long zi = (cg2 & ~15L) + pl16((int)(cg2 & 15));
    if (j >= 384) {
        for (int b = 0; b < BGRAPH; b++) z[(size_t)b*ZP + zi] = __half(0.f);
        return;
    }
    float s = 0.f, ss = 0.f;
    for (int b = 0; b < BGRAPH; b++) { float v = hp[b*384 + j]; s += v; ss += v*v; }
    float m = s*(1.f/BGRAPH);
    float var = ss*(1.f/BGRAPH) - m*m;
    float sc = rsqrtf(var + EPSV)*g[j];
    float bb = be[j];
    for (int b = 0; b < BGRAPH; b++)
        z[(size_t)b*ZP + zi] = __float2half_rn((hp[b*384 + j] - m)*sc + bb);
}
__global__ void k_bn_relu(const float* __restrict__ X, const float* __restrict__ gam,
                          const float* __restrict__ bet, float* __restrict__ Y, int ncols)
{
    int col = blockIdx.x, t = threadIdx.x;
    float v = X[t*ncols + col];
    float s = v, ss = v*v;
    #pragma unroll
    for (int o = 16; o > 0; o >>= 1) {
        s  += __shfl_down_sync(0xffffffffu, s,  o);
        ss += __shfl_down_sync(0xffffffffu, ss, o);
    }
    __shared__ float ws[4], wss[4];
    __shared__ float sm, sscale;
    int wid = t >> 5, lane = t & 31;
    if (lane == 0) { ws[wid] = s; wss[wid] = ss; }
    __syncthreads();
    if (t == 0) {
        float S = ws[0]+ws[1]+ws[2]+ws[3];
        float SS = wss[0]+wss[1]+wss[2]+wss[3];
        float m = S*(1.f/BGRAPH);
        sm = m; sscale = rsqrtf(SS*(1.f/BGRAPH) - m*m + EPSV);
    }
    __syncthreads();
    float o = (v - sm)*sscale*gam[col] + bet[col];
    Y[t*ncols + col] = fmaxf(o, 0.f);
}
__global__ void k_head(const float* __restrict__ a3, const float* __restrict__ W4,
                       const float* __restrict__ b4, float* __restrict__ out)
{
    int b = blockIdx.x, lane = threadIdx.x;
    float s0 = 0.f, s1 = 0.f;
    for (int i = lane; i < H2; i += 32) {
        float v = a3[b*H2 + i];
        s0 = fmaf(v, W4[i*2+0], s0);
        s1 = fmaf(v, W4[i*2+1], s1);
    }
    #pragma unroll
    for (int o = 16; o > 0; o >>= 1) {
        s0 += __shfl_down_sync(0xffffffffu, s0, o);
        s1 += __shfl_down_sync(0xffffffffu, s1, o);
    }
    if (lane == 0) {
        float l0 = s0 + b4[0], l1 = s1 + b4[1];
        float m = fmaxf(l0, l1);
        float lse = m + logf(expf(l0-m) + expf(l1-m));
        out[b*2+0] = l0 - lse;
        out[b*2+1] = l1 - lse;
    }
}

// ---------------- launch ----------------
extern "C" void kernel_launch(void* const* d_in, const int* in_sizes, int n_in,
                              void* d_out, int out_size)
{
    const float* x    = (const float*)d_in[0];
    const int*   esrc = (const int*)d_in[1];
    const int*   edst = (const int*)d_in[2];
    const float* Wc1  = (const float*)d_in[4];
    const float* bc1  = (const float*)d_in[5];
    const float* Wc2  = (const float*)d_in[6];
    const float* bc2  = (const float*)d_in[7];
    const float* Wc3  = (const float*)d_in[8];
    const float* bc3  = (const float*)d_in[9];
    const float* bn_g = (const float*)d_in[10];
    const float* bn_b = (const float*)d_in[11];
    const float* bnh_g= (const float*)d_in[12];
    const float* bnh_b= (const float*)d_in[13];
    const float* W1   = (const float*)d_in[14];
    const float* b1   = (const float*)d_in[15];
    const float* g1   = (const float*)d_in[16];
    const float* be1  = (const float*)d_in[17];
    const float* W2   = (const float*)d_in[18];
    const float* b2   = (const float*)d_in[19];
    const float* g2   = (const float*)d_in[20];
    const float* be2  = (const float*)d_in[21];
    const float* W3   = (const float*)d_in[22];
    const float* b3   = (const float*)d_in[23];
    const float* g3   = (const float*)d_in[24];
    const float* be3  = (const float*)d_in[25];
    const float* W4   = (const float*)d_in[26];
    const float* b4   = (const float*)d_in[27];
    float* out = (float*)d_out;

    const int DSMH = 4*9216*2;   // 73728 B (4-stage)
    cudaFuncSetAttribute((const void*)gkh<0,0>, cudaFuncAttributeMaxDynamicSharedMemorySize, DSMH);
    cudaFuncSetAttribute((const void*)gkh<1,0>, cudaFuncAttributeMaxDynamicSharedMemorySize, DSMH);
    cudaFuncSetAttribute((const void*)gkh<1,1>, cudaFuncAttributeMaxDynamicSharedMemorySize, DSMH);
    cudaFuncSetAttribute((const void*)gkh<2,0>, cudaFuncAttributeMaxDynamicSharedMemorySize, DSMH);

    void *pDinv, *pAh, *pXh, *pHh, *pX1, *pX2, *pX3, *pZh, *pW1h, *pHp, *pA1, *pA2, *pA3, *pWh;
    cudaGetSymbolAddress(&pDinv, g_dinv);
    cudaGetSymbolAddress(&pAh,  g_Ah);
    cudaGetSymbolAddress(&pXh,  g_xh);
    cudaGetSymbolAddress(&pHh,  g_hh);
    cudaGetSymbolAddress(&pX1,  g_x1h);
    cudaGetSymbolAddress(&pX2,  g_x2h);
    cudaGetSymbolAddress(&pX3,  g_x3h);
    cudaGetSymbolAddress(&pZh,  g_zh);
    cudaGetSymbolAddress(&pW1h, g_w1h);
    cudaGetSymbolAddress(&pHp,  g_hpool);
    cudaGetSymbolAddress(&pA1,  g_a1);
    cudaGetSymbolAddress(&pA2,  g_a2);
    cudaGetSymbolAddress(&pA3,  g_a3);
    cudaGetSymbolAddress(&pWh,  g_wh);

    const __half* wh = (const __half*)pWh;
    const __half* xh = (const __half*)pXh;
    const __half* Ah = (const __half*)pAh;
    const __half* hh = (const __half*)pHh;
    const __half* zh = (const __half*)pZh;
    const __half* w1h = (const __half*)pW1h;

    cudaStream_t s1, s2;
    cudaStreamCreateWithFlags(&s1, cudaStreamNonBlocking);
    cudaStreamCreateWithFlags(&s2, cudaStreamNonBlocking);
    cudaEvent_t eFork, eAdj, eZ, eX1, eX2, ePool;
    cudaEventCreateWithFlags(&eFork, cudaEventDisableTiming);
    cudaEventCreateWithFlags(&eAdj,  cudaEventDisableTiming);
    cudaEventCreateWithFlags(&eZ,    cudaEventDisableTiming);
    cudaEventCreateWithFlags(&eX1,   cudaEventDisableTiming);
    cudaEventCreateWithFlags(&eX2,   cudaEventDisableTiming);
    cudaEventCreateWithFlags(&ePool, cudaEventDisableTiming);

    cudaEventRecord(eFork, 0);
    cudaStreamWaitEvent(s1, eFork, 0);
    cudaStreamWaitEvent(s2, eFork, 0);

    // s1: adjacency chain + pools for layers 1-2
    cudaMemsetAsync(pDinv, 0, (size_t)NNODE*4, s1);
    cudaMemsetAsync(pAh, 0, (size_t)BGRAPH*AP*AP*2, s1);
    k_count_deg<<<(NEDGE+255)/256, 256, 0, s1>>>(edst);
    k_make_dinv<<<(NNODE+255)/256, 256, 0, s1>>>();
    k_build<<<(NEDGE+NNODE+255)/256, 256, 0, s1>>>(esrc, edst);
    cudaEventRecord(eAdj, s1);

    // s2: W1 conversion + triu BN + early zW1
    k_w1h<<<dim3(ZP/64, H1/32), 256, 0, s2>>>(W1);
    k_x0_bn<<<FN, 384, 0, s2>>>(x, bn_g, bn_b, (__half*)pZh);
    cudaMemsetAsync(pA1, 0, (size_t)BGRAPH*H1*4, s2);
    gkh<2,0><<<dim3(2,4,63), 256, DSMH, s2>>>(zh, w1h, nullptr, nullptr, (float*)pA1,
                                              nullptr, ZP, ZP, BGRAPH, 1024, 0);
    cudaEventRecord(eZ, s2);

    // s0: xh first (longest prep), then XW1 + fused AH chain
    k_xh<<<(NNODE*(AP/16)+255)/256, 256>>>(x);
    cudaMemsetAsync(pHh, 0, (size_t)BGRAPH*CCH*AP*2, 0);
    k_prep<<<(3*CCH*(AP/16)+255)/256, 256>>>(Wc1, Wc2, Wc3);
    gkh<0,0><<<dim3(720,1), 256, DSMH>>>(xh, wh, nullptr, nullptr, nullptr, nullptr,
                                         AP, AP, NNODE, AP, 0);
    cudaStreamWaitEvent(0, eAdj, 0);
    gkh<1,1><<<dim3(6,BGRAPH), 256, DSMH>>>(Ah, hh, bc1, (__half*)pX1, nullptr,
                                            wh + (size_t)CCH*AP, AP, AP, FN, AP, 0);
    cudaEventRecord(eX1, 0);
    gkh<1,1><<<dim3(6,BGRAPH), 256, DSMH>>>(Ah, hh, bc2, (__half*)pX2, nullptr,
                                            wh + (size_t)2*CCH*AP, AP, AP, FN, AP, 0);
    cudaEventRecord(eX2, 0);
    gkh<1,0><<<dim3(6,BGRAPH), 256, DSMH>>>(Ah, hh, bc3, (__half*)pX3, nullptr,
                                            nullptr, AP, AP, FN, AP, 0);

    // s1: pools for layers 1-2 overlap AH2/AH3
    cudaStreamWaitEvent(s1, eX1, 0);
    k_pool<<<BGRAPH, CCH, 0, s1>>>((const __half*)pX1, (float*)pHp, 0);
    cudaStreamWaitEvent(s1, eX2, 0);
    k_pool<<<BGRAPH, CCH, 0, s1>>>((const __half*)pX2, (float*)pHp, 1);
    cudaEventRecord(ePool, s1);

    // s0: pool3 + BN + last zW1 + fused-BN MLP tail
    k_pool<<<BGRAPH, CCH>>>((const __half*)pX3, (float*)pHp, 2);
    cudaStreamWaitEvent(0, ePool, 0);
    k_bn_pool<<<1, 1024>>>((const float*)pHp, bnh_g, bnh_b, (__half*)pZh);
    cudaStreamWaitEvent(0, eZ, 0);
    gkh<2,0><<<dim3(2,4,1), 256, DSMH>>>(zh, w1h, nullptr, nullptr, (float*)pA1,
                                         nullptr, ZP, ZP, BGRAPH, 1024, 64512);
    mmakBN<<<dim3(1,2), 256>>>((const float*)pA1, W2, g1, be1, (float*)pA2, BGRAPH, H2, H1);
    mmakBN<<<dim3(1,2), 256>>>((const float*)pA2, W3, g2, be2, (float*)pA3, BGRAPH, H2, H2);
    k_bn_relu<<<H2, 128>>>((const float*)pA3, g3, be3, (float*)pA3, H2);
    k_head<<<BGRAPH, 32>>>((const float*)pA3, W4, b4, out);

    cudaEventDestroy(eFork);
    cudaEventDestroy(eAdj);
    cudaEventDestroy(eZ);
    cudaEventDestroy(eX1);
    cudaEventDestroy(eX2);
    cudaEventDestroy(ePool);
    cudaStreamDestroy(s1);
    cudaStreamDestroy(s2);
}